// round 6
// baseline (speedup 1.0000x reference)
#include <cuda_runtime.h>
#include <math.h>
#include <stdint.h>

#define NE 200000
#define NU 100000
#define NEDGE 1000000
#define HDIM 128

// ---------------- scratch (static device arrays; no allocation) ----------------
__device__ float g_xe[(size_t)NE * HDIM];     // xe, later reused for e2
__device__ float g_accE[(size_t)NE * HDIM];
__device__ float g_accE2[(size_t)NE * HDIM];
__device__ float g_e1[(size_t)NE * HDIM];
__device__ float g_accU[(size_t)NU * HDIM];
__device__ float g_u1[(size_t)NU * HDIM];
__device__ float g_h[(size_t)NE * 64];
__device__ float g_cntE[NE];
__device__ float g_cntU[NU];
// transposed + column-DUPLICATED weights: [K][256], w[k][2c]=w[k][2c+1]=W[c][k]
__device__ float g_wTe[64 * 256];
__device__ float g_wT1n[128 * 256];
__device__ float g_wT1r[128 * 256];
__device__ float g_wT2n[128 * 256];
__device__ float g_wT2r[128 * 256];
__device__ float g_wT3n[128 * 256];
__device__ float g_wT3r[128 * 256];

// ---------------- f32x2 packed helpers ----------------
__device__ __forceinline__ void fma_x2(unsigned long long& acc, unsigned long long a,
                                       unsigned long long b) {
    asm("fma.rn.f32x2 %0, %1, %2, %0;" : "+l"(acc) : "l"(a), "l"(b));
}
__device__ __forceinline__ void mul_x2(unsigned long long& acc, unsigned long long s) {
    asm("mul.rn.f32x2 %0, %0, %1;" : "+l"(acc) : "l"(s));
}
__device__ __forceinline__ unsigned long long dup_x2(float v) {
    unsigned long long r;
    asm("mov.b64 %0, {%1, %1};" : "=l"(r) : "f"(v));
    return r;
}
__device__ __forceinline__ unsigned long long pack_x2(float lo, float hi) {
    unsigned long long r;
    asm("mov.b64 %0, {%1, %2};" : "=l"(r) : "f"(lo), "f"(hi));
    return r;
}
__device__ __forceinline__ void unpack_x2(unsigned long long v, float& lo, float& hi) {
    asm("mov.b64 {%0, %1}, %2;" : "=f"(lo), "=f"(hi) : "l"(v));
}
__device__ __forceinline__ uint32_t smem_u32(const void* p) {
    return (uint32_t)__cvta_generic_to_shared(p);
}
__device__ __forceinline__ void cp_async16(uint32_t dst, const void* src) {
    asm volatile("cp.async.ca.shared.global [%0], [%1], 16;" :: "r"(dst), "l"(src));
}
__device__ __forceinline__ void cp_commit() { asm volatile("cp.async.commit_group;"); }
__device__ __forceinline__ void cp_wait_all() {
    asm volatile("cp.async.wait_group 0;" ::: "memory");
}

// ---------------- init: zero accumulators + transpose/duplicate weights ----------
__global__ void init_kernel(const float* we, const float* w1n, const float* w1r,
                            const float* w2n, const float* w2r,
                            const float* w3n, const float* w3r)
{
    int i = blockIdx.x * blockDim.x + threadIdx.x;
    int stride = gridDim.x * blockDim.x;
    // zero (float4 views)
    const int nE4 = NE * HDIM / 4, nU4 = NU * HDIM / 4;
    const int cE4 = NE / 4, cU4 = NU / 4;
    float4 z = make_float4(0.f, 0.f, 0.f, 0.f);
    float4* aE  = (float4*)g_accE;
    float4* aE2 = (float4*)g_accE2;
    float4* aU  = (float4*)g_accU;
    for (int k = i; k < nE4; k += stride) { aE[k] = z; aE2[k] = z; }
    for (int k = i; k < nU4; k += stride) aU[k] = z;
    for (int k = i; k < cE4; k += stride) ((float4*)g_cntE)[k] = z;
    for (int k = i; k < cU4; k += stride) ((float4*)g_cntU)[k] = z;
    // transpose + duplicate: email (64x128 src)
    for (int k = i; k < 64 * 128; k += stride) {
        int kk = k >> 7, c = k & 127;
        float v = we[c * 64 + kk];
        g_wTe[kk * 256 + 2 * c] = v;
        g_wTe[kk * 256 + 2 * c + 1] = v;
    }
    // 6 matrices of 128x128
    for (int k = i; k < 6 * 128 * 128; k += stride) {
        int m = k >> 14, r = k & 16383;
        int kk = r >> 7, c = r & 127;
        const float* src;
        float* dst;
        switch (m) {
            case 0: src = w1n; dst = g_wT1n; break;
            case 1: src = w1r; dst = g_wT1r; break;
            case 2: src = w2n; dst = g_wT2n; break;
            case 3: src = w2r; dst = g_wT2r; break;
            case 4: src = w3n; dst = g_wT3n; break;
            default: src = w3r; dst = g_wT3r; break;
        }
        float v = src[c * 128 + kk];
        dst[kk * 256 + 2 * c] = v;
        dst[kk * 256 + 2 * c + 1] = v;
    }
}

// ---------------- edge scatter: one warp per 8 edges (MLP=8), vector RED --------
__global__ void scatter_kernel(const int* __restrict__ src, const int* __restrict__ dst,
                               const float* __restrict__ xsrc,
                               float* __restrict__ accum, float* __restrict__ cnt,
                               int doCnt)
{
    int warp = (blockIdx.x * blockDim.x + threadIdx.x) >> 5;
    int lane = threadIdx.x & 31;
    int e0 = warp * 8;
    if (e0 >= NEDGE) return;
    int4 sa = *reinterpret_cast<const int4*>(src + e0);
    int4 sb = *reinterpret_cast<const int4*>(src + e0 + 4);
    int4 da = *reinterpret_cast<const int4*>(dst + e0);
    int4 db = *reinterpret_cast<const int4*>(dst + e0 + 4);
    int s[8] = {sa.x, sa.y, sa.z, sa.w, sb.x, sb.y, sb.z, sb.w};
    int d[8] = {da.x, da.y, da.z, da.w, db.x, db.y, db.z, db.w};
    float4 v[8];
#pragma unroll
    for (int i = 0; i < 8; i++)
        v[i] = *reinterpret_cast<const float4*>(xsrc + (size_t)s[i] * HDIM + lane * 4);
#pragma unroll
    for (int i = 0; i < 8; i++) {
        float* a = accum + (size_t)d[i] * HDIM + lane * 4;
        asm volatile("red.global.add.v4.f32 [%0], {%1, %2, %3, %4};"
                     :: "l"(a), "f"(v[i].x), "f"(v[i].y), "f"(v[i].z), "f"(v[i].w) : "memory");
    }
    if (doCnt && lane == 0) {
#pragma unroll
        for (int i = 0; i < 8; i++) {
            float one = 1.0f;
            asm volatile("red.global.add.f32 [%0], %1;" :: "l"(cnt + d[i]), "f"(one) : "memory");
        }
    }
}

// ---------------- fused combine GEMM ----------------
// W given pre-transposed+duplicated [K][256]. BM=128, BN=128, BK=32, 256 threads.
// Thread (ty,tx): rows ty*8..+7 (4 f32x2 pairs), cols {tx+16j, j=0..7}.
template<bool HAS_A2, bool RELU, bool MEAN>
__global__ void __launch_bounds__(256, 2)
gemm_combine(const float* __restrict__ A1, int K1,
             const float* __restrict__ W1T,
             const float* __restrict__ A2,
             const float* __restrict__ W2T,
             const float* __restrict__ bias,
             const float* __restrict__ cnt,
             float* __restrict__ out, int M)
{
    __shared__ __align__(16) float As[2][32][132];  // [kk][r]; 528B pitch (16B mult)
    __shared__ __align__(16) float Ws[2][32][260];  // [kk][2c dup]; 1040B pitch
    int tid = threadIdx.x;
    int ty = tid >> 4, tx = tid & 15;
    int row0 = blockIdx.x * 128;

    const int nt1 = K1 >> 5;
    const int total = nt1 + (HAS_A2 ? 4 : 0);

    unsigned long long acc[4][8];
#pragma unroll
    for (int p = 0; p < 4; p++)
#pragma unroll
        for (int j = 0; j < 8; j++) acc[p][j] = 0ULL;

    auto cp_w = [&](int t, int buf) {
        const float* WT = (t < nt1) ? W1T : W2T;
        int k0 = (t < nt1) ? (t << 5) : ((t - nt1) << 5);
#pragma unroll
        for (int it = 0; it < 8; it++) {
            int idx = tid + it * 256;         // 2048 float4-chunks: kk=idx>>6, c4=idx&63
            int kk = idx >> 6, c4 = idx & 63;
            cp_async16(smem_u32(&Ws[buf][kk][c4 * 4]),
                       WT + (size_t)(k0 + kk) * 256 + c4 * 4);
        }
        cp_commit();
    };
    auto ldg_a = [&](int t, float4 la[4]) {
        const float* A; int K, k0;
        if (t < nt1) { A = A1; K = K1; k0 = t << 5; }
        else         { A = A2; K = 128; k0 = (t - nt1) << 5; }
#pragma unroll
        for (int it = 0; it < 4; it++) {
            int idx = tid + it * 256;
            int r = idx >> 3, q = idx & 7;
            int gr = row0 + r;
            la[it] = (gr < M) ? *reinterpret_cast<const float4*>(A + (size_t)gr * K + k0 + q * 4)
                              : make_float4(0.f, 0.f, 0.f, 0.f);
        }
    };
    auto sts_a = [&](const float4 la[4], int buf) {
#pragma unroll
        for (int it = 0; it < 4; it++) {
            int idx = tid + it * 256;
            int r = idx >> 3, q = idx & 7;
            As[buf][q * 4 + 0][r] = la[it].x;
            As[buf][q * 4 + 1][r] = la[it].y;
            As[buf][q * 4 + 2][r] = la[it].z;
            As[buf][q * 4 + 3][r] = la[it].w;
        }
    };

    {   // prologue
        float4 la[4];
        ldg_a(0, la);
        cp_w(0, 0);
        sts_a(la, 0);
        cp_wait_all();
    }
    __syncthreads();

    for (int t = 0; t < total; t++) {
        int cur = t & 1;
        float4 la[4];
        if (t + 1 < total) { ldg_a(t + 1, la); cp_w(t + 1, cur ^ 1); }
#pragma unroll
        for (int kk = 0; kk < 32; kk++) {
            longlong2 av0 = *reinterpret_cast<const longlong2*>(&As[cur][kk][ty * 8]);
            longlong2 av1 = *reinterpret_cast<const longlong2*>(&As[cur][kk][ty * 8 + 4]);
            unsigned long long a2[4] = {(unsigned long long)av0.x, (unsigned long long)av0.y,
                                        (unsigned long long)av1.x, (unsigned long long)av1.y};
            unsigned long long wd[8];
#pragma unroll
            for (int j = 0; j < 8; j++)
                wd[j] = *reinterpret_cast<const unsigned long long*>(&Ws[cur][kk][2 * (tx + 16 * j)]);
#pragma unroll
            for (int p = 0; p < 4; p++)
#pragma unroll
                for (int j = 0; j < 8; j++) fma_x2(acc[p][j], a2[p], wd[j]);
        }
        if (MEAN && t == nt1 - 1) {   // fold 1/cnt between phases
#pragma unroll
            for (int p = 0; p < 4; p++) {
                int gr0 = row0 + ty * 8 + 2 * p;
                int gr1 = gr0 + 1;
                float c0 = (gr0 < M) ? cnt[gr0] : 1.f;
                float c1 = (gr1 < M) ? cnt[gr1] : 1.f;
                unsigned long long invp = pack_x2(1.f / fmaxf(c0, 1.f), 1.f / fmaxf(c1, 1.f));
#pragma unroll
                for (int j = 0; j < 8; j++) mul_x2(acc[p][j], invp);
            }
        }
        if (t + 1 < total) { sts_a(la, cur ^ 1); cp_wait_all(); }
        __syncthreads();
    }

    float bj[8];
#pragma unroll
    for (int j = 0; j < 8; j++) bj[j] = bias[tx + 16 * j];

#pragma unroll
    for (int p = 0; p < 4; p++) {
        int gr0 = row0 + ty * 8 + 2 * p;
        int gr1 = gr0 + 1;
        float r0[8], r1[8];
#pragma unroll
        for (int j = 0; j < 8; j++) {
            unpack_x2(acc[p][j], r0[j], r1[j]);
            r0[j] += bj[j]; r1[j] += bj[j];
            if (RELU) { r0[j] = fmaxf(r0[j], 0.f); r1[j] = fmaxf(r1[j], 0.f); }
        }
        if (gr0 < M) {
#pragma unroll
            for (int j = 0; j < 8; j++) out[(size_t)gr0 * 128 + tx + 16 * j] = r0[j];
        }
        if (gr1 < M) {
#pragma unroll
            for (int j = 0; j < 8; j++) out[(size_t)gr1 * 128 + tx + 16 * j] = r1[j];
        }
    }
}

// ---------------- B-spline bases (uniform grid, grid_size=5, k=3 -> 8 bases) ----
__device__ __forceinline__ void bspline8(float x, float b[8]) {
    const float hstep = 2.0f / 5.0f;
    float g[12];
#pragma unroll
    for (int t = 0; t < 12; t++) g[t] = (float)(t - 3) * hstep - 1.0f;
    float p0[11], p1[10], p2[9];
#pragma unroll
    for (int t = 0; t < 11; t++) p0[t] = (x >= g[t] && x < g[t + 1]) ? 1.0f : 0.0f;
#pragma unroll
    for (int t = 0; t < 10; t++)
        p1[t] = (x - g[t]) * (1.0f / (g[t + 1] - g[t])) * p0[t]
              + (g[t + 2] - x) * (1.0f / (g[t + 2] - g[t + 1])) * p0[t + 1];
#pragma unroll
    for (int t = 0; t < 9; t++)
        p2[t] = (x - g[t]) * (1.0f / (g[t + 2] - g[t])) * p1[t]
              + (g[t + 3] - x) * (1.0f / (g[t + 3] - g[t + 1])) * p1[t + 1];
#pragma unroll
    for (int t = 0; t < 8; t++)
        b[t] = (x - g[t]) * (1.0f / (g[t + 3] - g[t])) * p2[t]
             + (g[t + 4] - x) * (1.0f / (g[t + 4] - g[t + 1])) * p2[t + 1];
}

__device__ __forceinline__ float silu(float x) {
    return x / (1.0f + __expf(-x));
}

// ---------------- KAN layer 1: [M,128] -> [M,64], duplicated-W smem --------------
// Thread (ty,tx): rows ty*8..+7 (4 f32x2 pairs), cols {tx+16j, j=0..3}.
__global__ void __launch_bounds__(256, 2)
kan1_kernel(const float* __restrict__ x,      // [M,128]
            const float* __restrict__ spline,  // [64,128,8]
            const float* __restrict__ scaler,  // [64,128]
            const float* __restrict__ basew,   // [64,128]
            float* __restrict__ out, int M)    // [M,64]
{
    __shared__ __align__(16) float Bs[2][32][132];
    __shared__ __align__(16) float Ws[2][32][132];  // duplicated pairs: cols 0..127
    int tid = threadIdx.x;
    int ty = tid >> 4, tx = tid & 15;
    int row0 = blockIdx.x * 128;
    unsigned long long acc[4][4];
#pragma unroll
    for (int p = 0; p < 4; p++)
#pragma unroll
        for (int j = 0; j < 4; j++) acc[p][j] = 0ULL;

    // --- spline phase: 32 chunks of 4 input features (32 basis K each), pipelined
    auto fill_chunk = [&](int c, float nb[2][8], float nw[8]) {
        int f0 = c * 4;
#pragma unroll
        for (int it = 0; it < 2; it++) {
            int p = tid + it * 256;
            int feat = p & 3, r = p >> 2;
            int gr = row0 + r;
            float xv = (gr < M) ? x[(size_t)gr * 128 + f0 + feat] : 0.f;
            bspline8(xv, nb[it]);
        }
#pragma unroll
        for (int it = 0; it < 8; it++) {
            int idx = tid + it * 256;
            int kk = idx & 31, col = idx >> 5;
            nw[it] = spline[(size_t)col * 1024 + f0 * 8 + kk] * scaler[col * 128 + f0 + (kk >> 3)];
        }
    };
    auto sts_chunk = [&](const float nb[2][8], const float nw[8], int buf) {
#pragma unroll
        for (int it = 0; it < 2; it++) {
            int p = tid + it * 256;
            int feat = p & 3, r = p >> 2;
#pragma unroll
            for (int t = 0; t < 8; t++) Bs[buf][feat * 8 + t][r] = nb[it][t];
        }
#pragma unroll
        for (int it = 0; it < 8; it++) {
            int idx = tid + it * 256;
            int kk = idx & 31, col = idx >> 5;
            *reinterpret_cast<unsigned long long*>(&Ws[buf][kk][2 * col]) = dup_x2(nw[it]);
        }
    };

    {
        float nb[2][8], nw[8];
        fill_chunk(0, nb, nw);
        sts_chunk(nb, nw, 0);
    }
    __syncthreads();

    for (int c = 0; c < 32; c++) {
        int cur = c & 1;
        float nb[2][8], nw[8];
        if (c + 1 < 32) fill_chunk(c + 1, nb, nw);
#pragma unroll
        for (int kk = 0; kk < 32; kk++) {
            longlong2 av0 = *reinterpret_cast<const longlong2*>(&Bs[cur][kk][ty * 8]);
            longlong2 av1 = *reinterpret_cast<const longlong2*>(&Bs[cur][kk][ty * 8 + 4]);
            unsigned long long a2[4] = {(unsigned long long)av0.x, (unsigned long long)av0.y,
                                        (unsigned long long)av1.x, (unsigned long long)av1.y};
            unsigned long long wd[4];
#pragma unroll
            for (int j = 0; j < 4; j++)
                wd[j] = *reinterpret_cast<const unsigned long long*>(&Ws[cur][kk][2 * (tx + 16 * j)]);
#pragma unroll
            for (int p = 0; p < 4; p++)
#pragma unroll
                for (int j = 0; j < 4; j++) fma_x2(acc[p][j], a2[p], wd[j]);
        }
        if (c + 1 < 32) sts_chunk(nb, nw, cur ^ 1);
        __syncthreads();
    }

    // --- base phase: silu(x) @ base_w^T, 4 chunks of 32 features
    for (int f0 = 0; f0 < 128; f0 += 32) {
#pragma unroll
        for (int it = 0; it < 16; it++) {
            int p = tid + it * 256;
            int feat = p & 31, r = p >> 5;
            int gr = row0 + r;
            float xv = (gr < M) ? x[(size_t)gr * 128 + f0 + feat] : 0.f;
            Bs[0][feat][r] = silu(xv);
        }
#pragma unroll
        for (int it = 0; it < 8; it++) {
            int idx = tid + it * 256;
            int kk = idx & 31, col = idx >> 5;
            *reinterpret_cast<unsigned long long*>(&Ws[0][kk][2 * col]) =
                dup_x2(basew[(size_t)col * 128 + f0 + kk]);
        }
        __syncthreads();
#pragma unroll
        for (int kk = 0; kk < 32; kk++) {
            longlong2 av0 = *reinterpret_cast<const longlong2*>(&Bs[0][kk][ty * 8]);
            longlong2 av1 = *reinterpret_cast<const longlong2*>(&Bs[0][kk][ty * 8 + 4]);
            unsigned long long a2[4] = {(unsigned long long)av0.x, (unsigned long long)av0.y,
                                        (unsigned long long)av1.x, (unsigned long long)av1.y};
            unsigned long long wd[4];
#pragma unroll
            for (int j = 0; j < 4; j++)
                wd[j] = *reinterpret_cast<const unsigned long long*>(&Ws[0][kk][2 * (tx + 16 * j)]);
#pragma unroll
            for (int p = 0; p < 4; p++)
#pragma unroll
                for (int j = 0; j < 4; j++) fma_x2(acc[p][j], a2[p], wd[j]);
        }
        __syncthreads();
    }

#pragma unroll
    for (int p = 0; p < 4; p++) {
        int gr0 = row0 + ty * 8 + 2 * p;
        int gr1 = gr0 + 1;
        float r0[4], r1[4];
#pragma unroll
        for (int j = 0; j < 4; j++) unpack_x2(acc[p][j], r0[j], r1[j]);
        if (gr0 < M) {
#pragma unroll
            for (int j = 0; j < 4; j++) out[(size_t)gr0 * 64 + tx + 16 * j] = r0[j];
        }
        if (gr1 < M) {
#pragma unroll
            for (int j = 0; j < 4; j++) out[(size_t)gr1 * 64 + tx + 16 * j] = r1[j];
        }
    }
}

// ---------------- KAN layer 2: [M,64] -> [M,2], one thread per row ----------------
__global__ void kan2_kernel(const float* __restrict__ hin,
                            const float* __restrict__ spline,
                            const float* __restrict__ scaler,
                            const float* __restrict__ basew,
                            float* __restrict__ out, int M)
{
    __shared__ float sh[128][65];
    __shared__ float sw[2][64][8];
    __shared__ float sb[2][64];
    int tid = threadIdx.x;
    int row0 = blockIdx.x * 128;
    for (int idx = tid; idx < 1024; idx += 128) {
        int o = idx >> 9, rem = idx & 511, f = rem >> 3, t = rem & 7;
        sw[o][f][t] = spline[idx] * scaler[o * 64 + f];
    }
    if (tid < 128) sb[tid >> 6][tid & 63] = basew[tid];
    for (int idx = tid; idx < 128 * 64; idx += 128) {
        int r = idx >> 6, f = idx & 63;
        int gr = row0 + r;
        sh[r][f] = (gr < M) ? hin[(size_t)gr * 64 + f] : 0.f;
    }
    __syncthreads();
    int gr = row0 + tid;
    if (gr >= M) return;
    float acc0 = 0.f, acc1 = 0.f;
    for (int f = 0; f < 64; f++) {
        float xv = sh[tid][f];
        float s = silu(xv);
        acc0 += s * sb[0][f];
        acc1 += s * sb[1][f];
        float b[8];
        bspline8(xv, b);
#pragma unroll
        for (int t = 0; t < 8; t++) {
            acc0 += b[t] * sw[0][f][t];
            acc1 += b[t] * sw[1][f][t];
        }
    }
    out[(size_t)gr * 2 + 0] = acc0;
    out[(size_t)gr * 2 + 1] = acc1;
}

// ---------------- launch ----------------
extern "C" void kernel_launch(void* const* d_in, const int* in_sizes, int n_in,
                              void* d_out, int out_size)
{
    const float* x_email    = (const float*)d_in[0];
    const int*   ei_ue      = (const int*)d_in[1];
    const int*   ei_eu      = (const int*)d_in[2];
    const float* w_email    = (const float*)d_in[3];
    const float* b_email    = (const float*)d_in[4];
    const float* emb_user   = (const float*)d_in[5];
    const float* w_l1_ue_n  = (const float*)d_in[6];
    const float* b_l1_ue    = (const float*)d_in[7];
    const float* w_l1_ue_r  = (const float*)d_in[8];
    const float* w_l1_eu_n  = (const float*)d_in[9];
    const float* b_l1_eu    = (const float*)d_in[10];
    const float* w_l1_eu_r  = (const float*)d_in[11];
    const float* w_l2_ue_n  = (const float*)d_in[12];
    const float* b_l2_ue    = (const float*)d_in[13];
    const float* w_l2_ue_r  = (const float*)d_in[14];
    const float* kan1_base   = (const float*)d_in[18];
    const float* kan1_spline = (const float*)d_in[19];
    const float* kan1_scaler = (const float*)d_in[20];
    const float* kan2_base   = (const float*)d_in[22];
    const float* kan2_spline = (const float*)d_in[23];
    const float* kan2_scaler = (const float*)d_in[24];
    float* out = (float*)d_out;

    float *xe, *accE, *accE2, *e1, *accU, *u1, *hbuf, *cntE, *cntU;
    cudaGetSymbolAddress((void**)&xe,    g_xe);
    cudaGetSymbolAddress((void**)&accE,  g_accE);
    cudaGetSymbolAddress((void**)&accE2, g_accE2);
    cudaGetSymbolAddress((void**)&e1,    g_e1);
    cudaGetSymbolAddress((void**)&accU,  g_accU);
    cudaGetSymbolAddress((void**)&u1,    g_u1);
    cudaGetSymbolAddress((void**)&hbuf,  g_h);
    cudaGetSymbolAddress((void**)&cntE,  g_cntE);
    cudaGetSymbolAddress((void**)&cntU,  g_cntU);
    float *wTe, *wT1n, *wT1r, *wT2n, *wT2r, *wT3n, *wT3r;
    cudaGetSymbolAddress((void**)&wTe,  g_wTe);
    cudaGetSymbolAddress((void**)&wT1n, g_wT1n);
    cudaGetSymbolAddress((void**)&wT1r, g_wT1r);
    cudaGetSymbolAddress((void**)&wT2n, g_wT2n);
    cudaGetSymbolAddress((void**)&wT2r, g_wT2r);
    cudaGetSymbolAddress((void**)&wT3n, g_wT3n);
    cudaGetSymbolAddress((void**)&wT3r, g_wT3r);

    int gE = (NE + 127) / 128;   // 1563
    int gU = (NU + 127) / 128;   // 782
    int gScat = (NEDGE / 8 * 32 + 255) / 256;  // 15625

    // 0: init (zero + weight transpose/duplicate) — single launch
    init_kernel<<<4096, 256>>>(w_email, w_l1_ue_n, w_l1_ue_r,
                               w_l1_eu_n, w_l1_eu_r, w_l2_ue_n, w_l2_ue_r);
    // 1: xe = x_email @ w_email^T + b_email
    gemm_combine<false, false, false><<<gE, 256>>>(x_email, 64, wTe,
                                                   nullptr, nullptr, b_email,
                                                   nullptr, xe, NE);
    // 2: conv1 email aggregate
    scatter_kernel<<<gScat, 256>>>(ei_ue, ei_ue + NEDGE, emb_user, accE, cntE, 1);
    // 3: conv1 email combine
    gemm_combine<true, true, true><<<gE, 256>>>(accE, 128, wT1n,
                                                xe, wT1r, b_l1_ue,
                                                cntE, e1, NE);
    // 4: conv1 user aggregate
    scatter_kernel<<<gScat, 256>>>(ei_eu, ei_eu + NEDGE, xe, accU, cntU, 1);
    // 5: conv1 user combine  (this is launch #6 — ncu -s 5 lands here)
    gemm_combine<true, true, true><<<gU, 256>>>(accU, 128, wT2n,
                                                emb_user, wT2r, b_l1_eu,
                                                cntU, u1, NU);
    // 6: conv2 email aggregate (separate pre-zeroed accumulator)
    scatter_kernel<<<gScat, 256>>>(ei_ue, ei_ue + NEDGE, u1, accE2, nullptr, 0);
    // 7: conv2 email combine
    gemm_combine<true, true, true><<<gE, 256>>>(accE2, 128, wT3n,
                                                e1, wT3r, b_l2_ue,
                                                cntE, xe /*= e2*/, NE);
    // 8-9: KAN head
    kan1_kernel<<<gE, 256>>>(xe, kan1_spline, kan1_scaler, kan1_base, hbuf, NE);
    kan2_kernel<<<gE, 128>>>(hbuf, kan2_spline, kan2_scaler, kan2_base, out, NE);
}

// round 7
// speedup vs baseline: 1.0041x; 1.0041x over previous
#include <cuda_runtime.h>
#include <math.h>
#include <stdint.h>

#define NE 200000
#define NU 100000
#define NEDGE 1000000
#define HDIM 128

// ---------------- scratch (static device arrays; no allocation) ----------------
__device__ float g_xe[(size_t)NE * HDIM];     // xe, later reused for e2
__device__ float g_accE[(size_t)NE * HDIM];
__device__ float g_accE2[(size_t)NE * HDIM];
__device__ float g_e1[(size_t)NE * HDIM];
__device__ float g_accU[(size_t)NU * HDIM];
__device__ float g_u1[(size_t)NU * HDIM];
__device__ float g_h[(size_t)NE * 64];
__device__ float g_cntE[NE];
__device__ float g_cntU[NU];
// transposed + column-DUPLICATED weights: [K][256], w[k][2c]=w[k][2c+1]=W[c][k]
__device__ float g_wTe[64 * 256];
__device__ float g_wT1n[128 * 256];
__device__ float g_wT1r[128 * 256];
__device__ float g_wT2n[128 * 256];
__device__ float g_wT2r[128 * 256];
__device__ float g_wT3n[128 * 256];
__device__ float g_wT3r[128 * 256];

// ---------------- f32x2 packed helpers ----------------
__device__ __forceinline__ void fma_x2(unsigned long long& acc, unsigned long long a,
                                       unsigned long long b) {
    asm("fma.rn.f32x2 %0, %1, %2, %0;" : "+l"(acc) : "l"(a), "l"(b));
}
__device__ __forceinline__ void mul_x2(unsigned long long& acc, unsigned long long s) {
    asm("mul.rn.f32x2 %0, %0, %1;" : "+l"(acc) : "l"(s));
}
__device__ __forceinline__ unsigned long long dup_x2(float v) {
    unsigned long long r;
    asm("mov.b64 %0, {%1, %1};" : "=l"(r) : "f"(v));
    return r;
}
__device__ __forceinline__ unsigned long long pack_x2(float lo, float hi) {
    unsigned long long r;
    asm("mov.b64 %0, {%1, %2};" : "=l"(r) : "f"(lo), "f"(hi));
    return r;
}
__device__ __forceinline__ void unpack_x2(unsigned long long v, float& lo, float& hi) {
    asm("mov.b64 {%0, %1}, %2;" : "=f"(lo), "=f"(hi) : "l"(v));
}
__device__ __forceinline__ uint32_t smem_u32(const void* p) {
    return (uint32_t)__cvta_generic_to_shared(p);
}
__device__ __forceinline__ void cp_async16(uint32_t dst, const void* src) {
    asm volatile("cp.async.ca.shared.global [%0], [%1], 16;" :: "r"(dst), "l"(src));
}
__device__ __forceinline__ void cp_commit() { asm volatile("cp.async.commit_group;"); }
__device__ __forceinline__ void cp_wait_all() {
    asm volatile("cp.async.wait_group 0;" ::: "memory");
}

// ---------------- init: zero accumulators + transpose/duplicate weights ----------
__global__ void init_kernel(const float* we, const float* w1n, const float* w1r,
                            const float* w2n, const float* w2r,
                            const float* w3n, const float* w3r)
{
    int i = blockIdx.x * blockDim.x + threadIdx.x;
    int stride = gridDim.x * blockDim.x;
    const int nE4 = NE * HDIM / 4, nU4 = NU * HDIM / 4;
    const int cE4 = NE / 4, cU4 = NU / 4;
    float4 z = make_float4(0.f, 0.f, 0.f, 0.f);
    float4* aE  = (float4*)g_accE;
    float4* aE2 = (float4*)g_accE2;
    float4* aU  = (float4*)g_accU;
    for (int k = i; k < nE4; k += stride) { aE[k] = z; aE2[k] = z; }
    for (int k = i; k < nU4; k += stride) aU[k] = z;
    for (int k = i; k < cE4; k += stride) ((float4*)g_cntE)[k] = z;
    for (int k = i; k < cU4; k += stride) ((float4*)g_cntU)[k] = z;
    for (int k = i; k < 64 * 128; k += stride) {
        int kk = k >> 7, c = k & 127;
        float v = we[c * 64 + kk];
        g_wTe[kk * 256 + 2 * c] = v;
        g_wTe[kk * 256 + 2 * c + 1] = v;
    }
    for (int k = i; k < 6 * 128 * 128; k += stride) {
        int m = k >> 14, r = k & 16383;
        int kk = r >> 7, c = r & 127;
        const float* src;
        float* dst;
        switch (m) {
            case 0: src = w1n; dst = g_wT1n; break;
            case 1: src = w1r; dst = g_wT1r; break;
            case 2: src = w2n; dst = g_wT2n; break;
            case 3: src = w2r; dst = g_wT2r; break;
            case 4: src = w3n; dst = g_wT3n; break;
            default: src = w3r; dst = g_wT3r; break;
        }
        float v = src[c * 128 + kk];
        dst[kk * 256 + 2 * c] = v;
        dst[kk * 256 + 2 * c + 1] = v;
    }
}

// ---------------- edge scatter: one warp per 8 edges (MLP=8), vector RED --------
__global__ void scatter_kernel(const int* __restrict__ src, const int* __restrict__ dst,
                               const float* __restrict__ xsrc,
                               float* __restrict__ accum, float* __restrict__ cnt,
                               int doCnt)
{
    int warp = (blockIdx.x * blockDim.x + threadIdx.x) >> 5;
    int lane = threadIdx.x & 31;
    int e0 = warp * 8;
    if (e0 >= NEDGE) return;
    int4 sa = *reinterpret_cast<const int4*>(src + e0);
    int4 sb = *reinterpret_cast<const int4*>(src + e0 + 4);
    int4 da = *reinterpret_cast<const int4*>(dst + e0);
    int4 db = *reinterpret_cast<const int4*>(dst + e0 + 4);
    int s[8] = {sa.x, sa.y, sa.z, sa.w, sb.x, sb.y, sb.z, sb.w};
    int d[8] = {da.x, da.y, da.z, da.w, db.x, db.y, db.z, db.w};
    float4 v[8];
#pragma unroll
    for (int i = 0; i < 8; i++)
        v[i] = *reinterpret_cast<const float4*>(xsrc + (size_t)s[i] * HDIM + lane * 4);
#pragma unroll
    for (int i = 0; i < 8; i++) {
        float* a = accum + (size_t)d[i] * HDIM + lane * 4;
        asm volatile("red.global.add.v4.f32 [%0], {%1, %2, %3, %4};"
                     :: "l"(a), "f"(v[i].x), "f"(v[i].y), "f"(v[i].z), "f"(v[i].w) : "memory");
    }
    if (doCnt && lane == 0) {
#pragma unroll
        for (int i = 0; i < 8; i++) {
            float one = 1.0f;
            asm volatile("red.global.add.f32 [%0], %1;" :: "l"(cnt + d[i]), "f"(one) : "memory");
        }
    }
}

// ---------------- fused combine GEMM (unchanged from R6 — measured 326us) --------
template<bool HAS_A2, bool RELU, bool MEAN>
__global__ void __launch_bounds__(256, 2)
gemm_combine(const float* __restrict__ A1, int K1,
             const float* __restrict__ W1T,
             const float* __restrict__ A2,
             const float* __restrict__ W2T,
             const float* __restrict__ bias,
             const float* __restrict__ cnt,
             float* __restrict__ out, int M)
{
    __shared__ __align__(16) float As[2][32][132];
    __shared__ __align__(16) float Ws[2][32][260];
    int tid = threadIdx.x;
    int ty = tid >> 4, tx = tid & 15;
    int row0 = blockIdx.x * 128;

    const int nt1 = K1 >> 5;
    const int total = nt1 + (HAS_A2 ? 4 : 0);

    unsigned long long acc[4][8];
#pragma unroll
    for (int p = 0; p < 4; p++)
#pragma unroll
        for (int j = 0; j < 8; j++) acc[p][j] = 0ULL;

    auto cp_w = [&](int t, int buf) {
        const float* WT = (t < nt1) ? W1T : W2T;
        int k0 = (t < nt1) ? (t << 5) : ((t - nt1) << 5);
#pragma unroll
        for (int it = 0; it < 8; it++) {
            int idx = tid + it * 256;
            int kk = idx >> 6, c4 = idx & 63;
            cp_async16(smem_u32(&Ws[buf][kk][c4 * 4]),
                       WT + (size_t)(k0 + kk) * 256 + c4 * 4);
        }
        cp_commit();
    };
    auto ldg_a = [&](int t, float4 la[4]) {
        const float* A; int K, k0;
        if (t < nt1) { A = A1; K = K1; k0 = t << 5; }
        else         { A = A2; K = 128; k0 = (t - nt1) << 5; }
#pragma unroll
        for (int it = 0; it < 4; it++) {
            int idx = tid + it * 256;
            int r = idx >> 3, q = idx & 7;
            int gr = row0 + r;
            la[it] = (gr < M) ? *reinterpret_cast<const float4*>(A + (size_t)gr * K + k0 + q * 4)
                              : make_float4(0.f, 0.f, 0.f, 0.f);
        }
    };
    auto sts_a = [&](const float4 la[4], int buf) {
#pragma unroll
        for (int it = 0; it < 4; it++) {
            int idx = tid + it * 256;
            int r = idx >> 3, q = idx & 7;
            As[buf][q * 4 + 0][r] = la[it].x;
            As[buf][q * 4 + 1][r] = la[it].y;
            As[buf][q * 4 + 2][r] = la[it].z;
            As[buf][q * 4 + 3][r] = la[it].w;
        }
    };

    {
        float4 la[4];
        ldg_a(0, la);
        cp_w(0, 0);
        sts_a(la, 0);
        cp_wait_all();
    }
    __syncthreads();

    for (int t = 0; t < total; t++) {
        int cur = t & 1;
        float4 la[4];
        if (t + 1 < total) { ldg_a(t + 1, la); cp_w(t + 1, cur ^ 1); }
#pragma unroll
        for (int kk = 0; kk < 32; kk++) {
            longlong2 av0 = *reinterpret_cast<const longlong2*>(&As[cur][kk][ty * 8]);
            longlong2 av1 = *reinterpret_cast<const longlong2*>(&As[cur][kk][ty * 8 + 4]);
            unsigned long long a2[4] = {(unsigned long long)av0.x, (unsigned long long)av0.y,
                                        (unsigned long long)av1.x, (unsigned long long)av1.y};
            unsigned long long wd[8];
#pragma unroll
            for (int j = 0; j < 8; j++)
                wd[j] = *reinterpret_cast<const unsigned long long*>(&Ws[cur][kk][2 * (tx + 16 * j)]);
#pragma unroll
            for (int p = 0; p < 4; p++)
#pragma unroll
                for (int j = 0; j < 8; j++) fma_x2(acc[p][j], a2[p], wd[j]);
        }
        if (MEAN && t == nt1 - 1) {
#pragma unroll
            for (int p = 0; p < 4; p++) {
                int gr0 = row0 + ty * 8 + 2 * p;
                int gr1 = gr0 + 1;
                float c0 = (gr0 < M) ? cnt[gr0] : 1.f;
                float c1 = (gr1 < M) ? cnt[gr1] : 1.f;
                unsigned long long invp = pack_x2(1.f / fmaxf(c0, 1.f), 1.f / fmaxf(c1, 1.f));
#pragma unroll
                for (int j = 0; j < 8; j++) mul_x2(acc[p][j], invp);
            }
        }
        if (t + 1 < total) { sts_a(la, cur ^ 1); cp_wait_all(); }
        __syncthreads();
    }

    float bj[8];
#pragma unroll
    for (int j = 0; j < 8; j++) bj[j] = bias[tx + 16 * j];

#pragma unroll
    for (int p = 0; p < 4; p++) {
        int gr0 = row0 + ty * 8 + 2 * p;
        int gr1 = gr0 + 1;
        float r0[8], r1[8];
#pragma unroll
        for (int j = 0; j < 8; j++) {
            unpack_x2(acc[p][j], r0[j], r1[j]);
            r0[j] += bj[j]; r1[j] += bj[j];
            if (RELU) { r0[j] = fmaxf(r0[j], 0.f); r1[j] = fmaxf(r1[j], 0.f); }
        }
        if (gr0 < M) {
#pragma unroll
            for (int j = 0; j < 8; j++) out[(size_t)gr0 * 128 + tx + 16 * j] = r0[j];
        }
        if (gr1 < M) {
#pragma unroll
            for (int j = 0; j < 8; j++) out[(size_t)gr1 * 128 + tx + 16 * j] = r1[j];
        }
    }
}

// ---------------- B-spline bases (uniform grid, grid_size=5, k=3 -> 8 bases) ----
__device__ __forceinline__ void bspline8(float x, float b[8]) {
    const float hstep = 2.0f / 5.0f;
    float g[12];
#pragma unroll
    for (int t = 0; t < 12; t++) g[t] = (float)(t - 3) * hstep - 1.0f;
    float p0[11], p1[10], p2[9];
#pragma unroll
    for (int t = 0; t < 11; t++) p0[t] = (x >= g[t] && x < g[t + 1]) ? 1.0f : 0.0f;
#pragma unroll
    for (int t = 0; t < 10; t++)
        p1[t] = (x - g[t]) * (1.0f / (g[t + 1] - g[t])) * p0[t]
              + (g[t + 2] - x) * (1.0f / (g[t + 2] - g[t + 1])) * p0[t + 1];
#pragma unroll
    for (int t = 0; t < 9; t++)
        p2[t] = (x - g[t]) * (1.0f / (g[t + 2] - g[t])) * p1[t]
              + (g[t + 3] - x) * (1.0f / (g[t + 3] - g[t + 1])) * p1[t + 1];
#pragma unroll
    for (int t = 0; t < 8; t++)
        b[t] = (x - g[t]) * (1.0f / (g[t + 3] - g[t])) * p2[t]
             + (g[t + 4] - x) * (1.0f / (g[t + 4] - g[t + 1])) * p2[t + 1];
}

__device__ __forceinline__ float silu(float x) {
    return x / (1.0f + __expf(-x));
}

// ---------------- KAN layer 1: regs unconstrained (NO min-blocks — spill trap) ----
__global__ void __launch_bounds__(256)
kan1_kernel(const float* __restrict__ x,      // [M,128]
            const float* __restrict__ spline,  // [64,128,8]
            const float* __restrict__ scaler,  // [64,128]
            const float* __restrict__ basew,   // [64,128]
            float* __restrict__ out, int M)    // [M,64]
{
    __shared__ __align__(16) float Bs[2][32][132];
    __shared__ __align__(16) float Ws[2][32][132];  // duplicated pairs: cols 0..127
    int tid = threadIdx.x;
    int ty = tid >> 4, tx = tid & 15;
    int row0 = blockIdx.x * 128;
    unsigned long long acc[4][4];
#pragma unroll
    for (int p = 0; p < 4; p++)
#pragma unroll
        for (int j = 0; j < 4; j++) acc[p][j] = 0ULL;

    auto fill_chunk = [&](int c, float nb[2][8], float nw[8]) {
        int f0 = c * 4;
#pragma unroll
        for (int it = 0; it < 2; it++) {
            int p = tid + it * 256;
            int feat = p & 3, r = p >> 2;
            int gr = row0 + r;
            float xv = (gr < M) ? x[(size_t)gr * 128 + f0 + feat] : 0.f;
            bspline8(xv, nb[it]);
        }
#pragma unroll
        for (int it = 0; it < 8; it++) {
            int idx = tid + it * 256;
            int kk = idx & 31, col = idx >> 5;
            nw[it] = spline[(size_t)col * 1024 + f0 * 8 + kk] * scaler[col * 128 + f0 + (kk >> 3)];
        }
    };
    auto sts_chunk = [&](const float nb[2][8], const float nw[8], int buf) {
#pragma unroll
        for (int it = 0; it < 2; it++) {
            int p = tid + it * 256;
            int feat = p & 3, r = p >> 2;
#pragma unroll
            for (int t = 0; t < 8; t++) Bs[buf][feat * 8 + t][r] = nb[it][t];
        }
#pragma unroll
        for (int it = 0; it < 8; it++) {
            int idx = tid + it * 256;
            int kk = idx & 31, col = idx >> 5;
            *reinterpret_cast<unsigned long long*>(&Ws[buf][kk][2 * col]) = dup_x2(nw[it]);
        }
    };

    {
        float nb[2][8], nw[8];
        fill_chunk(0, nb, nw);
        sts_chunk(nb, nw, 0);
    }
    __syncthreads();

    for (int c = 0; c < 32; c++) {
        int cur = c & 1;
        float nb[2][8], nw[8];
        if (c + 1 < 32) fill_chunk(c + 1, nb, nw);
#pragma unroll
        for (int kk = 0; kk < 32; kk++) {
            longlong2 av0 = *reinterpret_cast<const longlong2*>(&Bs[cur][kk][ty * 8]);
            longlong2 av1 = *reinterpret_cast<const longlong2*>(&Bs[cur][kk][ty * 8 + 4]);
            unsigned long long a2[4] = {(unsigned long long)av0.x, (unsigned long long)av0.y,
                                        (unsigned long long)av1.x, (unsigned long long)av1.y};
            unsigned long long wd[4];
#pragma unroll
            for (int j = 0; j < 4; j++)
                wd[j] = *reinterpret_cast<const unsigned long long*>(&Ws[cur][kk][2 * (tx + 16 * j)]);
#pragma unroll
            for (int p = 0; p < 4; p++)
#pragma unroll
                for (int j = 0; j < 4; j++) fma_x2(acc[p][j], a2[p], wd[j]);
        }
        if (c + 1 < 32) sts_chunk(nb, nw, cur ^ 1);
        __syncthreads();
    }

    for (int f0 = 0; f0 < 128; f0 += 32) {
#pragma unroll
        for (int it = 0; it < 16; it++) {
            int p = tid + it * 256;
            int feat = p & 31, r = p >> 5;
            int gr = row0 + r;
            float xv = (gr < M) ? x[(size_t)gr * 128 + f0 + feat] : 0.f;
            Bs[0][feat][r] = silu(xv);
        }
#pragma unroll
        for (int it = 0; it < 8; it++) {
            int idx = tid + it * 256;
            int kk = idx & 31, col = idx >> 5;
            *reinterpret_cast<unsigned long long*>(&Ws[0][kk][2 * col]) =
                dup_x2(basew[(size_t)col * 128 + f0 + kk]);
        }
        __syncthreads();
#pragma unroll
        for (int kk = 0; kk < 32; kk++) {
            longlong2 av0 = *reinterpret_cast<const longlong2*>(&Bs[0][kk][ty * 8]);
            longlong2 av1 = *reinterpret_cast<const longlong2*>(&Bs[0][kk][ty * 8 + 4]);
            unsigned long long a2[4] = {(unsigned long long)av0.x, (unsigned long long)av0.y,
                                        (unsigned long long)av1.x, (unsigned long long)av1.y};
            unsigned long long wd[4];
#pragma unroll
            for (int j = 0; j < 4; j++)
                wd[j] = *reinterpret_cast<const unsigned long long*>(&Ws[0][kk][2 * (tx + 16 * j)]);
#pragma unroll
            for (int p = 0; p < 4; p++)
#pragma unroll
                for (int j = 0; j < 4; j++) fma_x2(acc[p][j], a2[p], wd[j]);
        }
        __syncthreads();
    }

#pragma unroll
    for (int p = 0; p < 4; p++) {
        int gr0 = row0 + ty * 8 + 2 * p;
        int gr1 = gr0 + 1;
        float r0[4], r1[4];
#pragma unroll
        for (int j = 0; j < 4; j++) unpack_x2(acc[p][j], r0[j], r1[j]);
        if (gr0 < M) {
#pragma unroll
            for (int j = 0; j < 4; j++) out[(size_t)gr0 * 64 + tx + 16 * j] = r0[j];
        }
        if (gr1 < M) {
#pragma unroll
            for (int j = 0; j < 4; j++) out[(size_t)gr1 * 64 + tx + 16 * j] = r1[j];
        }
    }
}

// ---------------- KAN layer 2: [M,64] -> [M,2], one thread per row ----------------
__global__ void kan2_kernel(const float* __restrict__ hin,
                            const float* __restrict__ spline,
                            const float* __restrict__ scaler,
                            const float* __restrict__ basew,
                            float* __restrict__ out, int M)
{
    __shared__ float sh[128][65];
    __shared__ float sw[2][64][8];
    __shared__ float sb[2][64];
    int tid = threadIdx.x;
    int row0 = blockIdx.x * 128;
    for (int idx = tid; idx < 1024; idx += 128) {
        int o = idx >> 9, rem = idx & 511, f = rem >> 3, t = rem & 7;
        sw[o][f][t] = spline[idx] * scaler[o * 64 + f];
    }
    if (tid < 128) sb[tid >> 6][tid & 63] = basew[tid];
    for (int idx = tid; idx < 128 * 64; idx += 128) {
        int r = idx >> 6, f = idx & 63;
        int gr = row0 + r;
        sh[r][f] = (gr < M) ? hin[(size_t)gr * 64 + f] : 0.f;
    }
    __syncthreads();
    int gr = row0 + tid;
    if (gr >= M) return;
    float acc0 = 0.f, acc1 = 0.f;
    for (int f = 0; f < 64; f++) {
        float xv = sh[tid][f];
        float s = silu(xv);
        acc0 += s * sb[0][f];
        acc1 += s * sb[1][f];
        float b[8];
        bspline8(xv, b);
#pragma unroll
        for (int t = 0; t < 8; t++) {
            acc0 += b[t] * sw[0][f][t];
            acc1 += b[t] * sw[1][f][t];
        }
    }
    out[(size_t)gr * 2 + 0] = acc0;
    out[(size_t)gr * 2 + 1] = acc1;
}

// ---------------- launch ----------------
extern "C" void kernel_launch(void* const* d_in, const int* in_sizes, int n_in,
                              void* d_out, int out_size)
{
    const float* x_email    = (const float*)d_in[0];
    const int*   ei_ue      = (const int*)d_in[1];
    const int*   ei_eu      = (const int*)d_in[2];
    const float* w_email    = (const float*)d_in[3];
    const float* b_email    = (const float*)d_in[4];
    const float* emb_user   = (const float*)d_in[5];
    const float* w_l1_ue_n  = (const float*)d_in[6];
    const float* b_l1_ue    = (const float*)d_in[7];
    const float* w_l1_ue_r  = (const float*)d_in[8];
    const float* w_l1_eu_n  = (const float*)d_in[9];
    const float* b_l1_eu    = (const float*)d_in[10];
    const float* w_l1_eu_r  = (const float*)d_in[11];
    const float* w_l2_ue_n  = (const float*)d_in[12];
    const float* b_l2_ue    = (const float*)d_in[13];
    const float* w_l2_ue_r  = (const float*)d_in[14];
    const float* kan1_base   = (const float*)d_in[18];
    const float* kan1_spline = (const float*)d_in[19];
    const float* kan1_scaler = (const float*)d_in[20];
    const float* kan2_base   = (const float*)d_in[22];
    const float* kan2_spline = (const float*)d_in[23];
    const float* kan2_scaler = (const float*)d_in[24];
    float* out = (float*)d_out;

    float *xe, *accE, *accE2, *e1, *accU, *u1, *hbuf, *cntE, *cntU;
    cudaGetSymbolAddress((void**)&xe,    g_xe);
    cudaGetSymbolAddress((void**)&accE,  g_accE);
    cudaGetSymbolAddress((void**)&accE2, g_accE2);
    cudaGetSymbolAddress((void**)&e1,    g_e1);
    cudaGetSymbolAddress((void**)&accU,  g_accU);
    cudaGetSymbolAddress((void**)&u1,    g_u1);
    cudaGetSymbolAddress((void**)&hbuf,  g_h);
    cudaGetSymbolAddress((void**)&cntE,  g_cntE);
    cudaGetSymbolAddress((void**)&cntU,  g_cntU);
    float *wTe, *wT1n, *wT1r, *wT2n, *wT2r, *wT3n, *wT3r;
    cudaGetSymbolAddress((void**)&wTe,  g_wTe);
    cudaGetSymbolAddress((void**)&wT1n, g_wT1n);
    cudaGetSymbolAddress((void**)&wT1r, g_wT1r);
    cudaGetSymbolAddress((void**)&wT2n, g_wT2n);
    cudaGetSymbolAddress((void**)&wT2r, g_wT2r);
    cudaGetSymbolAddress((void**)&wT3n, g_wT3n);
    cudaGetSymbolAddress((void**)&wT3r, g_wT3r);

    int gE = (NE + 127) / 128;   // 1563
    int gU = (NU + 127) / 128;   // 782
    int gScat = (NEDGE / 8 * 32 + 255) / 256;  // 15625

    init_kernel<<<4096, 256>>>(w_email, w_l1_ue_n, w_l1_ue_r,
                               w_l1_eu_n, w_l1_eu_r, w_l2_ue_n, w_l2_ue_r);
    gemm_combine<false, false, false><<<gE, 256>>>(x_email, 64, wTe,
                                                   nullptr, nullptr, b_email,
                                                   nullptr, xe, NE);
    scatter_kernel<<<gScat, 256>>>(ei_ue, ei_ue + NEDGE, emb_user, accE, cntE, 1);
    gemm_combine<true, true, true><<<gE, 256>>>(accE, 128, wT1n,
                                                xe, wT1r, b_l1_ue,
                                                cntE, e1, NE);
    scatter_kernel<<<gScat, 256>>>(ei_eu, ei_eu + NEDGE, xe, accU, cntU, 1);
    gemm_combine<true, true, true><<<gU, 256>>>(accU, 128, wT2n,
                                                emb_user, wT2r, b_l1_eu,
                                                cntU, u1, NU);
    scatter_kernel<<<gScat, 256>>>(ei_ue, ei_ue + NEDGE, u1, accE2, nullptr, 0);
    gemm_combine<true, true, true><<<gE, 256>>>(accE2, 128, wT3n,
                                                e1, wT3r, b_l2_ue,
                                                cntE, xe /*= e2*/, NE);
    kan1_kernel<<<gE, 256>>>(xe, kan1_spline, kan1_scaler, kan1_base, hbuf, NE);
    kan2_kernel<<<gE, 128>>>(hbuf, kan2_spline, kan2_scaler, kan2_base, out, NE);
}

// round 8
// speedup vs baseline: 1.0670x; 1.0626x over previous
#include <cuda_runtime.h>
#include <math.h>
#include <stdint.h>

#define NE 200000
#define NU 100000
#define NEDGE 1000000
#define HDIM 128

// ---------------- scratch (static device arrays; no allocation) ----------------
__device__ float g_xe[(size_t)NE * HDIM];     // xe, later reused for e2
__device__ float g_accE[(size_t)NE * HDIM];
__device__ float g_accE2[(size_t)NE * HDIM];
__device__ float g_e1[(size_t)NE * HDIM];
__device__ float g_accU[(size_t)NU * HDIM];
__device__ float g_u1[(size_t)NU * HDIM];
__device__ float g_h[(size_t)NE * 64];
__device__ float g_cntE[NE];
__device__ float g_cntU[NU];
// transposed + column-DUPLICATED weights: [K][256], w[k][2c]=w[k][2c+1]=W[c][k]
__device__ float g_wTe[64 * 256];
__device__ float g_wT1n[128 * 256];
__device__ float g_wT1r[128 * 256];
__device__ float g_wT2n[128 * 256];
__device__ float g_wT2r[128 * 256];
__device__ float g_wT3n[128 * 256];
__device__ float g_wT3r[128 * 256];

// ---------------- f32x2 packed helpers ----------------
__device__ __forceinline__ void fma_x2(unsigned long long& acc, unsigned long long a,
                                       unsigned long long b) {
    asm("fma.rn.f32x2 %0, %1, %2, %0;" : "+l"(acc) : "l"(a), "l"(b));
}
__device__ __forceinline__ void mul_x2(unsigned long long& acc, unsigned long long s) {
    asm("mul.rn.f32x2 %0, %0, %1;" : "+l"(acc) : "l"(s));
}
__device__ __forceinline__ unsigned long long dup_x2(float v) {
    unsigned long long r;
    asm("mov.b64 %0, {%1, %1};" : "=l"(r) : "f"(v));
    return r;
}
__device__ __forceinline__ unsigned long long pack_x2(float lo, float hi) {
    unsigned long long r;
    asm("mov.b64 %0, {%1, %2};" : "=l"(r) : "f"(lo), "f"(hi));
    return r;
}
__device__ __forceinline__ void unpack_x2(unsigned long long v, float& lo, float& hi) {
    asm("mov.b64 {%0, %1}, %2;" : "=f"(lo), "=f"(hi) : "l"(v));
}
__device__ __forceinline__ uint32_t smem_u32(const void* p) {
    return (uint32_t)__cvta_generic_to_shared(p);
}
__device__ __forceinline__ void cp_async16(uint32_t dst, const void* src) {
    asm volatile("cp.async.ca.shared.global [%0], [%1], 16;" :: "r"(dst), "l"(src));
}
__device__ __forceinline__ void cp_commit() { asm volatile("cp.async.commit_group;"); }
__device__ __forceinline__ void cp_wait_all() {
    asm volatile("cp.async.wait_group 0;" ::: "memory");
}

// ---------------- init: zero accumulators + transpose/duplicate weights ----------
__global__ void init_kernel(const float* we, const float* w1n, const float* w1r,
                            const float* w2n, const float* w2r,
                            const float* w3n, const float* w3r)
{
    int i = blockIdx.x * blockDim.x + threadIdx.x;
    int stride = gridDim.x * blockDim.x;
    const int nE4 = NE * HDIM / 4, nU4 = NU * HDIM / 4;
    const int cE4 = NE / 4, cU4 = NU / 4;
    float4 z = make_float4(0.f, 0.f, 0.f, 0.f);
    float4* aE  = (float4*)g_accE;
    float4* aE2 = (float4*)g_accE2;
    float4* aU  = (float4*)g_accU;
    for (int k = i; k < nE4; k += stride) { aE[k] = z; aE2[k] = z; }
    for (int k = i; k < nU4; k += stride) aU[k] = z;
    for (int k = i; k < cE4; k += stride) ((float4*)g_cntE)[k] = z;
    for (int k = i; k < cU4; k += stride) ((float4*)g_cntU)[k] = z;
    for (int k = i; k < 64 * 128; k += stride) {
        int kk = k >> 7, c = k & 127;
        float v = we[c * 64 + kk];
        g_wTe[kk * 256 + 2 * c] = v;
        g_wTe[kk * 256 + 2 * c + 1] = v;
    }
    for (int k = i; k < 6 * 128 * 128; k += stride) {
        int m = k >> 14, r = k & 16383;
        int kk = r >> 7, c = r & 127;
        const float* src;
        float* dst;
        switch (m) {
            case 0: src = w1n; dst = g_wT1n; break;
            case 1: src = w1r; dst = g_wT1r; break;
            case 2: src = w2n; dst = g_wT2n; break;
            case 3: src = w2r; dst = g_wT2r; break;
            case 4: src = w3n; dst = g_wT3n; break;
            default: src = w3r; dst = g_wT3r; break;
        }
        float v = src[c * 128 + kk];
        dst[kk * 256 + 2 * c] = v;
        dst[kk * 256 + 2 * c + 1] = v;
    }
}

// ---------------- edge scatter: one warp per 8 edges (MLP=8), vector RED --------
__global__ void scatter_kernel(const int* __restrict__ src, const int* __restrict__ dst,
                               const float* __restrict__ xsrc,
                               float* __restrict__ accum, float* __restrict__ cnt,
                               int doCnt)
{
    int warp = (blockIdx.x * blockDim.x + threadIdx.x) >> 5;
    int lane = threadIdx.x & 31;
    int e0 = warp * 8;
    if (e0 >= NEDGE) return;
    int4 sa = *reinterpret_cast<const int4*>(src + e0);
    int4 sb = *reinterpret_cast<const int4*>(src + e0 + 4);
    int4 da = *reinterpret_cast<const int4*>(dst + e0);
    int4 db = *reinterpret_cast<const int4*>(dst + e0 + 4);
    int s[8] = {sa.x, sa.y, sa.z, sa.w, sb.x, sb.y, sb.z, sb.w};
    int d[8] = {da.x, da.y, da.z, da.w, db.x, db.y, db.z, db.w};
    float4 v[8];
#pragma unroll
    for (int i = 0; i < 8; i++)
        v[i] = *reinterpret_cast<const float4*>(xsrc + (size_t)s[i] * HDIM + lane * 4);
#pragma unroll
    for (int i = 0; i < 8; i++) {
        float* a = accum + (size_t)d[i] * HDIM + lane * 4;
        asm volatile("red.global.add.v4.f32 [%0], {%1, %2, %3, %4};"
                     :: "l"(a), "f"(v[i].x), "f"(v[i].y), "f"(v[i].z), "f"(v[i].w) : "memory");
    }
    if (doCnt && lane == 0) {
#pragma unroll
        for (int i = 0; i < 8; i++) {
            float one = 1.0f;
            asm volatile("red.global.add.f32 [%0], %1;" :: "l"(cnt + d[i]), "f"(one) : "memory");
        }
    }
}

// ---------------- fused combine GEMM (R6/R7 version — measured 326us) ------------
template<bool HAS_A2, bool RELU, bool MEAN>
__global__ void __launch_bounds__(256, 2)
gemm_combine(const float* __restrict__ A1, int K1,
             const float* __restrict__ W1T,
             const float* __restrict__ A2,
             const float* __restrict__ W2T,
             const float* __restrict__ bias,
             const float* __restrict__ cnt,
             float* __restrict__ out, int M)
{
    __shared__ __align__(16) float As[2][32][132];
    __shared__ __align__(16) float Ws[2][32][260];
    int tid = threadIdx.x;
    int ty = tid >> 4, tx = tid & 15;
    int row0 = blockIdx.x * 128;

    const int nt1 = K1 >> 5;
    const int total = nt1 + (HAS_A2 ? 4 : 0);

    unsigned long long acc[4][8];
#pragma unroll
    for (int p = 0; p < 4; p++)
#pragma unroll
        for (int j = 0; j < 8; j++) acc[p][j] = 0ULL;

    auto cp_w = [&](int t, int buf) {
        const float* WT = (t < nt1) ? W1T : W2T;
        int k0 = (t < nt1) ? (t << 5) : ((t - nt1) << 5);
#pragma unroll
        for (int it = 0; it < 8; it++) {
            int idx = tid + it * 256;
            int kk = idx >> 6, c4 = idx & 63;
            cp_async16(smem_u32(&Ws[buf][kk][c4 * 4]),
                       WT + (size_t)(k0 + kk) * 256 + c4 * 4);
        }
        cp_commit();
    };
    auto ldg_a = [&](int t, float4 la[4]) {
        const float* A; int K, k0;
        if (t < nt1) { A = A1; K = K1; k0 = t << 5; }
        else         { A = A2; K = 128; k0 = (t - nt1) << 5; }
#pragma unroll
        for (int it = 0; it < 4; it++) {
            int idx = tid + it * 256;
            int r = idx >> 3, q = idx & 7;
            int gr = row0 + r;
            la[it] = (gr < M) ? *reinterpret_cast<const float4*>(A + (size_t)gr * K + k0 + q * 4)
                              : make_float4(0.f, 0.f, 0.f, 0.f);
        }
    };
    auto sts_a = [&](const float4 la[4], int buf) {
#pragma unroll
        for (int it = 0; it < 4; it++) {
            int idx = tid + it * 256;
            int r = idx >> 3, q = idx & 7;
            As[buf][q * 4 + 0][r] = la[it].x;
            As[buf][q * 4 + 1][r] = la[it].y;
            As[buf][q * 4 + 2][r] = la[it].z;
            As[buf][q * 4 + 3][r] = la[it].w;
        }
    };

    {
        float4 la[4];
        ldg_a(0, la);
        cp_w(0, 0);
        sts_a(la, 0);
        cp_wait_all();
    }
    __syncthreads();

    for (int t = 0; t < total; t++) {
        int cur = t & 1;
        float4 la[4];
        if (t + 1 < total) { ldg_a(t + 1, la); cp_w(t + 1, cur ^ 1); }
#pragma unroll
        for (int kk = 0; kk < 32; kk++) {
            longlong2 av0 = *reinterpret_cast<const longlong2*>(&As[cur][kk][ty * 8]);
            longlong2 av1 = *reinterpret_cast<const longlong2*>(&As[cur][kk][ty * 8 + 4]);
            unsigned long long a2[4] = {(unsigned long long)av0.x, (unsigned long long)av0.y,
                                        (unsigned long long)av1.x, (unsigned long long)av1.y};
            unsigned long long wd[8];
#pragma unroll
            for (int j = 0; j < 8; j++)
                wd[j] = *reinterpret_cast<const unsigned long long*>(&Ws[cur][kk][2 * (tx + 16 * j)]);
#pragma unroll
            for (int p = 0; p < 4; p++)
#pragma unroll
                for (int j = 0; j < 8; j++) fma_x2(acc[p][j], a2[p], wd[j]);
        }
        if (MEAN && t == nt1 - 1) {
#pragma unroll
            for (int p = 0; p < 4; p++) {
                int gr0 = row0 + ty * 8 + 2 * p;
                int gr1 = gr0 + 1;
                float c0 = (gr0 < M) ? cnt[gr0] : 1.f;
                float c1 = (gr1 < M) ? cnt[gr1] : 1.f;
                unsigned long long invp = pack_x2(1.f / fmaxf(c0, 1.f), 1.f / fmaxf(c1, 1.f));
#pragma unroll
                for (int j = 0; j < 8; j++) mul_x2(acc[p][j], invp);
            }
        }
        if (t + 1 < total) { sts_a(la, cur ^ 1); cp_wait_all(); }
        __syncthreads();
    }

    float bj[8];
#pragma unroll
    for (int j = 0; j < 8; j++) bj[j] = bias[tx + 16 * j];

#pragma unroll
    for (int p = 0; p < 4; p++) {
        int gr0 = row0 + ty * 8 + 2 * p;
        int gr1 = gr0 + 1;
        float r0[8], r1[8];
#pragma unroll
        for (int j = 0; j < 8; j++) {
            unpack_x2(acc[p][j], r0[j], r1[j]);
            r0[j] += bj[j]; r1[j] += bj[j];
            if (RELU) { r0[j] = fmaxf(r0[j], 0.f); r1[j] = fmaxf(r1[j], 0.f); }
        }
        if (gr0 < M) {
#pragma unroll
            for (int j = 0; j < 8; j++) out[(size_t)gr0 * 128 + tx + 16 * j] = r0[j];
        }
        if (gr1 < M) {
#pragma unroll
            for (int j = 0; j < 8; j++) out[(size_t)gr1 * 128 + tx + 16 * j] = r1[j];
        }
    }
}

// ---------------- B-spline bases (uniform grid, grid_size=5, k=3 -> 8 bases) ----
__device__ __forceinline__ void bspline8(float x, float b[8]) {
    const float hstep = 2.0f / 5.0f;
    float g[12];
#pragma unroll
    for (int t = 0; t < 12; t++) g[t] = (float)(t - 3) * hstep - 1.0f;
    float p0[11], p1[10], p2[9];
#pragma unroll
    for (int t = 0; t < 11; t++) p0[t] = (x >= g[t] && x < g[t + 1]) ? 1.0f : 0.0f;
#pragma unroll
    for (int t = 0; t < 10; t++)
        p1[t] = ((x - g[t]) * (1.0f / (g[t + 1] - g[t]))) * p0[t]
              + ((g[t + 2] - x) * (1.0f / (g[t + 2] - g[t + 1]))) * p0[t + 1];
#pragma unroll
    for (int t = 0; t < 9; t++)
        p2[t] = ((x - g[t]) * (1.0f / (g[t + 2] - g[t]))) * p1[t]
              + ((g[t + 3] - x) * (1.0f / (g[t + 3] - g[t + 1]))) * p1[t + 1];
#pragma unroll
    for (int t = 0; t < 8; t++)
        b[t] = ((x - g[t]) * (1.0f / (g[t + 3] - g[t]))) * p2[t]
             + ((g[t + 4] - x) * (1.0f / (g[t + 4] - g[t + 1]))) * p2[t + 1];
}

__device__ __forceinline__ float silu(float x) {
    return x / (1.0f + __expf(-x));
}

// ---------------- KAN layer 1: EXACT R4-sub version (part of 2019.5us binary) ----
// Thread (ty,tx): rows ty*8..+7 (4 f32x2 pairs), cols {tx+16j, j=0..3}.
__global__ void __launch_bounds__(256)
kan1_kernel(const float* __restrict__ x,      // [M,128]
            const float* __restrict__ spline,  // [64,128,8]
            const float* __restrict__ scaler,  // [64,128]
            const float* __restrict__ basew,   // [64,128]
            float* __restrict__ out, int M)    // [M,64]
{
    __shared__ __align__(16) float Bs[2][32][130];
    __shared__ __align__(16) float Ws[2][32][66];
    int tid = threadIdx.x;
    int ty = tid >> 4, tx = tid & 15;
    int row0 = blockIdx.x * 128;
    unsigned long long acc[4][4];
#pragma unroll
    for (int p = 0; p < 4; p++)
#pragma unroll
        for (int j = 0; j < 4; j++) acc[p][j] = 0ULL;

    auto fill_chunk = [&](int c, float nb[2][8], float nw[8]) {
        int f0 = c * 4;
#pragma unroll
        for (int it = 0; it < 2; it++) {
            int p = tid + it * 256;
            int feat = p & 3, r = p >> 2;
            int gr = row0 + r;
            float xv = (gr < M) ? x[(size_t)gr * 128 + f0 + feat] : 0.f;
            bspline8(xv, nb[it]);
        }
#pragma unroll
        for (int it = 0; it < 8; it++) {
            int idx = tid + it * 256;
            int kk = idx & 31, col = idx >> 5;
            nw[it] = spline[(size_t)col * 1024 + f0 * 8 + kk] * scaler[col * 128 + f0 + (kk >> 3)];
        }
    };
    auto sts_chunk = [&](const float nb[2][8], const float nw[8], int buf) {
#pragma unroll
        for (int it = 0; it < 2; it++) {
            int p = tid + it * 256;
            int feat = p & 3, r = p >> 2;
#pragma unroll
            for (int t = 0; t < 8; t++) Bs[buf][feat * 8 + t][r] = nb[it][t];
        }
#pragma unroll
        for (int it = 0; it < 8; it++) {
            int idx = tid + it * 256;
            Ws[buf][idx & 31][idx >> 5] = nw[it];
        }
    };

    {
        float nb[2][8], nw[8];
        fill_chunk(0, nb, nw);
        sts_chunk(nb, nw, 0);
    }
    __syncthreads();

    for (int c = 0; c < 32; c++) {
        int cur = c & 1;
        float nb[2][8], nw[8];
        if (c + 1 < 32) fill_chunk(c + 1, nb, nw);
#pragma unroll
        for (int kk = 0; kk < 32; kk++) {
            unsigned long long a2[4];
#pragma unroll
            for (int p = 0; p < 4; p++)
                a2[p] = *reinterpret_cast<const unsigned long long*>(&Bs[cur][kk][ty * 8 + 2 * p]);
            unsigned long long wd[4];
#pragma unroll
            for (int j = 0; j < 4; j++) wd[j] = dup_x2(Ws[cur][kk][tx + 16 * j]);
#pragma unroll
            for (int p = 0; p < 4; p++)
#pragma unroll
                for (int j = 0; j < 4; j++) fma_x2(acc[p][j], a2[p], wd[j]);
        }
        if (c + 1 < 32) sts_chunk(nb, nw, cur ^ 1);
        __syncthreads();
    }

    for (int f0 = 0; f0 < 128; f0 += 32) {
#pragma unroll
        for (int it = 0; it < 16; it++) {
            int p = tid + it * 256;
            int feat = p & 31, r = p >> 5;
            int gr = row0 + r;
            float xv = (gr < M) ? x[(size_t)gr * 128 + f0 + feat] : 0.f;
            Bs[0][feat][r] = silu(xv);
        }
#pragma unroll
        for (int it = 0; it < 8; it++) {
            int idx = tid + it * 256;
            int kk = idx & 31, col = idx >> 5;
            Ws[0][kk][col] = basew[(size_t)col * 128 + f0 + kk];
        }
        __syncthreads();
#pragma unroll
        for (int kk = 0; kk < 32; kk++) {
            unsigned long long a2[4];
#pragma unroll
            for (int p = 0; p < 4; p++)
                a2[p] = *reinterpret_cast<const unsigned long long*>(&Bs[0][kk][ty * 8 + 2 * p]);
            unsigned long long wd[4];
#pragma unroll
            for (int j = 0; j < 4; j++) wd[j] = dup_x2(Ws[0][kk][tx + 16 * j]);
#pragma unroll
            for (int p = 0; p < 4; p++)
#pragma unroll
                for (int j = 0; j < 4; j++) fma_x2(acc[p][j], a2[p], wd[j]);
        }
        __syncthreads();
    }

#pragma unroll
    for (int p = 0; p < 4; p++) {
        int gr0 = row0 + ty * 8 + 2 * p;
        int gr1 = gr0 + 1;
        float r0[4], r1[4];
#pragma unroll
        for (int j = 0; j < 4; j++) unpack_x2(acc[p][j], r0[j], r1[j]);
        if (gr0 < M) {
#pragma unroll
            for (int j = 0; j < 4; j++) out[(size_t)gr0 * 64 + tx + 16 * j] = r0[j];
        }
        if (gr1 < M) {
#pragma unroll
            for (int j = 0; j < 4; j++) out[(size_t)gr1 * 64 + tx + 16 * j] = r1[j];
        }
    }
}

// ---------------- KAN layer 2: [M,64] -> [M,2], one thread per row ----------------
__global__ void kan2_kernel(const float* __restrict__ hin,
                            const float* __restrict__ spline,
                            const float* __restrict__ scaler,
                            const float* __restrict__ basew,
                            float* __restrict__ out, int M)
{
    __shared__ float sh[128][65];
    __shared__ float sw[2][64][8];
    __shared__ float sb[2][64];
    int tid = threadIdx.x;
    int row0 = blockIdx.x * 128;
    for (int idx = tid; idx < 1024; idx += 128) {
        int o = idx >> 9, rem = idx & 511, f = rem >> 3, t = rem & 7;
        sw[o][f][t] = spline[idx] * scaler[o * 64 + f];
    }
    if (tid < 128) sb[tid >> 6][tid & 63] = basew[tid];
    for (int idx = tid; idx < 128 * 64; idx += 128) {
        int r = idx >> 6, f = idx & 63;
        int gr = row0 + r;
        sh[r][f] = (gr < M) ? hin[(size_t)gr * 64 + f] : 0.f;
    }
    __syncthreads();
    int gr = row0 + tid;
    if (gr >= M) return;
    float acc0 = 0.f, acc1 = 0.f;
    for (int f = 0; f < 64; f++) {
        float xv = sh[tid][f];
        float s = silu(xv);
        acc0 += s * sb[0][f];
        acc1 += s * sb[1][f];
        float b[8];
        bspline8(xv, b);
#pragma unroll
        for (int t = 0; t < 8; t++) {
            acc0 += b[t] * sw[0][f][t];
            acc1 += b[t] * sw[1][f][t];
        }
    }
    out[(size_t)gr * 2 + 0] = acc0;
    out[(size_t)gr * 2 + 1] = acc1;
}

// ---------------- launch ----------------
extern "C" void kernel_launch(void* const* d_in, const int* in_sizes, int n_in,
                              void* d_out, int out_size)
{
    const float* x_email    = (const float*)d_in[0];
    const int*   ei_ue      = (const int*)d_in[1];
    const int*   ei_eu      = (const int*)d_in[2];
    const float* w_email    = (const float*)d_in[3];
    const float* b_email    = (const float*)d_in[4];
    const float* emb_user   = (const float*)d_in[5];
    const float* w_l1_ue_n  = (const float*)d_in[6];
    const float* b_l1_ue    = (const float*)d_in[7];
    const float* w_l1_ue_r  = (const float*)d_in[8];
    const float* w_l1_eu_n  = (const float*)d_in[9];
    const float* b_l1_eu    = (const float*)d_in[10];
    const float* w_l1_eu_r  = (const float*)d_in[11];
    const float* w_l2_ue_n  = (const float*)d_in[12];
    const float* b_l2_ue    = (const float*)d_in[13];
    const float* w_l2_ue_r  = (const float*)d_in[14];
    const float* kan1_base   = (const float*)d_in[18];
    const float* kan1_spline = (const float*)d_in[19];
    const float* kan1_scaler = (const float*)d_in[20];
    const float* kan2_base   = (const float*)d_in[22];
    const float* kan2_spline = (const float*)d_in[23];
    const float* kan2_scaler = (const float*)d_in[24];
    float* out = (float*)d_out;

    float *xe, *accE, *accE2, *e1, *accU, *u1, *hbuf, *cntE, *cntU;
    cudaGetSymbolAddress((void**)&xe,    g_xe);
    cudaGetSymbolAddress((void**)&accE,  g_accE);
    cudaGetSymbolAddress((void**)&accE2, g_accE2);
    cudaGetSymbolAddress((void**)&e1,    g_e1);
    cudaGetSymbolAddress((void**)&accU,  g_accU);
    cudaGetSymbolAddress((void**)&u1,    g_u1);
    cudaGetSymbolAddress((void**)&hbuf,  g_h);
    cudaGetSymbolAddress((void**)&cntE,  g_cntE);
    cudaGetSymbolAddress((void**)&cntU,  g_cntU);
    float *wTe, *wT1n, *wT1r, *wT2n, *wT2r, *wT3n, *wT3r;
    cudaGetSymbolAddress((void**)&wTe,  g_wTe);
    cudaGetSymbolAddress((void**)&wT1n, g_wT1n);
    cudaGetSymbolAddress((void**)&wT1r, g_wT1r);
    cudaGetSymbolAddress((void**)&wT2n, g_wT2n);
    cudaGetSymbolAddress((void**)&wT2r, g_wT2r);
    cudaGetSymbolAddress((void**)&wT3n, g_wT3n);
    cudaGetSymbolAddress((void**)&wT3r, g_wT3r);

    int gE = (NE + 127) / 128;   // 1563
    int gU = (NU + 127) / 128;   // 782
    int gScat = (NEDGE / 8 * 32 + 255) / 256;  // 15625

    init_kernel<<<4096, 256>>>(w_email, w_l1_ue_n, w_l1_ue_r,
                               w_l1_eu_n, w_l1_eu_r, w_l2_ue_n, w_l2_ue_r);
    gemm_combine<false, false, false><<<gE, 256>>>(x_email, 64, wTe,
                                                   nullptr, nullptr, b_email,
                                                   nullptr, xe, NE);
    scatter_kernel<<<gScat, 256>>>(ei_ue, ei_ue + NEDGE, emb_user, accE, cntE, 1);
    gemm_combine<true, true, true><<<gE, 256>>>(accE, 128, wT1n,
                                                xe, wT1r, b_l1_ue,
                                                cntE, e1, NE);
    scatter_kernel<<<gScat, 256>>>(ei_eu, ei_eu + NEDGE, xe, accU, cntU, 1);
    gemm_combine<true, true, true><<<gU, 256>>>(accU, 128, wT2n,
                                                emb_user, wT2r, b_l1_eu,
                                                cntU, u1, NU);
    scatter_kernel<<<gScat, 256>>>(ei_ue, ei_ue + NEDGE, u1, accE2, nullptr, 0);
    gemm_combine<true, true, true><<<gE, 256>>>(accE2, 128, wT3n,
                                                e1, wT3r, b_l2_ue,
                                                cntE, xe /*= e2*/, NE);
    kan1_kernel<<<gE, 256>>>(xe, kan1_spline, kan1_scaler, kan1_base, hbuf, NE);
    kan2_kernel<<<gE, 128>>>(hbuf, kan2_spline, kan2_scaler, kan2_base, out, NE);
}

// round 9
// speedup vs baseline: 1.1559x; 1.0832x over previous
#include <cuda_runtime.h>
#include <math.h>
#include <stdint.h>

#define NE 200000
#define NU 100000
#define NEDGE 1000000
#define HDIM 128

// ---------------- scratch (static device arrays; no allocation) ----------------
__device__ float g_xe[(size_t)NE * HDIM];     // xe, later reused for e2
__device__ float g_accE[(size_t)NE * HDIM];
__device__ float g_accE2[(size_t)NE * HDIM];
__device__ float g_e1[(size_t)NE * HDIM];
__device__ float g_accU[(size_t)NU * HDIM];
__device__ float g_u1[(size_t)NU * HDIM];
__device__ float g_h[(size_t)NE * 64];
__device__ float g_cntE[NE];
__device__ float g_cntU[NU];
// transposed weights: [K][128] (NON-duplicated — dup was net-negative, R8 post-mortem)
__device__ float g_wTe[64 * 128];
__device__ float g_wT1n[128 * 128];
__device__ float g_wT1r[128 * 128];
__device__ float g_wT2n[128 * 128];
__device__ float g_wT2r[128 * 128];
__device__ float g_wT3n[128 * 128];
__device__ float g_wT3r[128 * 128];

// ---------------- f32x2 packed helpers ----------------
__device__ __forceinline__ void fma_x2(unsigned long long& acc, unsigned long long a,
                                       unsigned long long b) {
    asm("fma.rn.f32x2 %0, %1, %2, %0;" : "+l"(acc) : "l"(a), "l"(b));
}
__device__ __forceinline__ void mul_x2(unsigned long long& acc, unsigned long long s) {
    asm("mul.rn.f32x2 %0, %0, %1;" : "+l"(acc) : "l"(s));
}
__device__ __forceinline__ unsigned long long dup_x2(float v) {
    unsigned long long r;
    asm("mov.b64 %0, {%1, %1};" : "=l"(r) : "f"(v));
    return r;
}
__device__ __forceinline__ unsigned long long pack_x2(float lo, float hi) {
    unsigned long long r;
    asm("mov.b64 %0, {%1, %2};" : "=l"(r) : "f"(lo), "f"(hi));
    return r;
}
__device__ __forceinline__ void unpack_x2(unsigned long long v, float& lo, float& hi) {
    asm("mov.b64 {%0, %1}, %2;" : "=f"(lo), "=f"(hi) : "l"(v));
}
__device__ __forceinline__ uint32_t smem_u32(const void* p) {
    return (uint32_t)__cvta_generic_to_shared(p);
}
__device__ __forceinline__ void cp_async16(uint32_t dst, const void* src) {
    asm volatile("cp.async.ca.shared.global [%0], [%1], 16;" :: "r"(dst), "l"(src));
}
__device__ __forceinline__ void cp_commit() { asm volatile("cp.async.commit_group;"); }
__device__ __forceinline__ void cp_wait_all() {
    asm volatile("cp.async.wait_group 0;" ::: "memory");
}

// ---------------- init: zero accumulators + transpose weights -------------------
__global__ void init_kernel(const float* we, const float* w1n, const float* w1r,
                            const float* w2n, const float* w2r,
                            const float* w3n, const float* w3r)
{
    int i = blockIdx.x * blockDim.x + threadIdx.x;
    int stride = gridDim.x * blockDim.x;
    const int nE4 = NE * HDIM / 4, nU4 = NU * HDIM / 4;
    const int cE4 = NE / 4, cU4 = NU / 4;
    float4 z = make_float4(0.f, 0.f, 0.f, 0.f);
    float4* aE  = (float4*)g_accE;
    float4* aE2 = (float4*)g_accE2;
    float4* aU  = (float4*)g_accU;
    for (int k = i; k < nE4; k += stride) { aE[k] = z; aE2[k] = z; }
    for (int k = i; k < nU4; k += stride) aU[k] = z;
    for (int k = i; k < cE4; k += stride) ((float4*)g_cntE)[k] = z;
    for (int k = i; k < cU4; k += stride) ((float4*)g_cntU)[k] = z;
    for (int k = i; k < 64 * 128; k += stride) {
        int kk = k >> 7, c = k & 127;
        g_wTe[k] = we[c * 64 + kk];
    }
    for (int k = i; k < 6 * 128 * 128; k += stride) {
        int m = k >> 14, r = k & 16383;
        int kk = r >> 7, c = r & 127;
        const float* src;
        float* dst;
        switch (m) {
            case 0: src = w1n; dst = g_wT1n; break;
            case 1: src = w1r; dst = g_wT1r; break;
            case 2: src = w2n; dst = g_wT2n; break;
            case 3: src = w2r; dst = g_wT2r; break;
            case 4: src = w3n; dst = g_wT3n; break;
            default: src = w3r; dst = g_wT3r; break;
        }
        dst[r] = src[c * 128 + kk];
    }
}

// ---------------- scatter body: one warp handles 8 edges (MLP=8) ----------------
__device__ __forceinline__ void scatter_body(int swarp, int lane,
                                             const int* __restrict__ src,
                                             const int* __restrict__ dst,
                                             const float* __restrict__ xsrc,
                                             float* __restrict__ accum,
                                             float* __restrict__ cnt, bool doCnt)
{
    int e0 = swarp * 8;
    if (e0 >= NEDGE) return;
    int4 sa = *reinterpret_cast<const int4*>(src + e0);
    int4 sb = *reinterpret_cast<const int4*>(src + e0 + 4);
    int4 da = *reinterpret_cast<const int4*>(dst + e0);
    int4 db = *reinterpret_cast<const int4*>(dst + e0 + 4);
    int s[8] = {sa.x, sa.y, sa.z, sa.w, sb.x, sb.y, sb.z, sb.w};
    int d[8] = {da.x, da.y, da.z, da.w, db.x, db.y, db.z, db.w};
    float4 v[8];
#pragma unroll
    for (int i = 0; i < 8; i++)
        v[i] = *reinterpret_cast<const float4*>(xsrc + (size_t)s[i] * HDIM + lane * 4);
#pragma unroll
    for (int i = 0; i < 8; i++) {
        float* a = accum + (size_t)d[i] * HDIM + lane * 4;
        asm volatile("red.global.add.v4.f32 [%0], {%1, %2, %3, %4};"
                     :: "l"(a), "f"(v[i].x), "f"(v[i].y), "f"(v[i].z), "f"(v[i].w) : "memory");
    }
    if (doCnt && lane == 0) {
#pragma unroll
        for (int i = 0; i < 8; i++) {
            float one = 1.0f;
            asm volatile("red.global.add.f32 [%0], %1;" :: "l"(cnt + d[i]), "f"(one) : "memory");
        }
    }
}

// ---------------- standalone scatter (for scatter3) ----------------
__global__ void scatter_kernel(const int* __restrict__ src, const int* __restrict__ dst,
                               const float* __restrict__ xsrc,
                               float* __restrict__ accum, float* __restrict__ cnt,
                               int doCnt)
{
    int swarp = (blockIdx.x * blockDim.x + threadIdx.x) >> 5;
    scatter_body(swarp, threadIdx.x & 31, src, dst, xsrc, accum, cnt, doCnt != 0);
}

// ---------------- GEMM body (R5-binary version: non-dup W, dup_x2 in loop) ------
// out[M,128] = epi( A1[M,K1]*(1/max(cnt,1)) @ W1T + (HAS_A2 ? A2 @ W2T : 0) + bias )
// W pre-transposed [K][128]. BM=128, BN=128, BK=32, 256 threads.
// Thread (ty,tx): rows ty*8..+7 (4 f32x2 pairs), cols {tx+16j, j=0..7}.
template<bool HAS_A2, bool RELU, bool MEAN>
__device__ __forceinline__ void gemm_body(int bid,
                                          const float* __restrict__ A1, int K1,
                                          const float* __restrict__ W1T,
                                          const float* __restrict__ A2,
                                          const float* __restrict__ W2T,
                                          const float* __restrict__ bias,
                                          const float* __restrict__ cnt,
                                          float* __restrict__ out, int M)
{
    __shared__ __align__(16) float As[2][32][132];
    __shared__ __align__(16) float Ws[2][32][132];
    int tid = threadIdx.x;
    int ty = tid >> 4, tx = tid & 15;
    int row0 = bid * 128;

    const int nt1 = K1 >> 5;
    const int total = nt1 + (HAS_A2 ? 4 : 0);

    unsigned long long acc[4][8];
#pragma unroll
    for (int p = 0; p < 4; p++)
#pragma unroll
        for (int j = 0; j < 8; j++) acc[p][j] = 0ULL;

    auto cp_w = [&](int t, int buf) {
        const float* WT = (t < nt1) ? W1T : W2T;
        int k0 = (t < nt1) ? (t << 5) : ((t - nt1) << 5);
#pragma unroll
        for (int it = 0; it < 4; it++) {
            int idx = tid + it * 256;
            int kk = idx >> 5, c4 = idx & 31;
            cp_async16(smem_u32(&Ws[buf][kk][c4 * 4]),
                       WT + (size_t)(k0 + kk) * 128 + c4 * 4);
        }
        cp_commit();
    };
    auto ldg_a = [&](int t, float4 la[4]) {
        const float* A; int K, k0;
        if (t < nt1) { A = A1; K = K1; k0 = t << 5; }
        else         { A = A2; K = 128; k0 = (t - nt1) << 5; }
#pragma unroll
        for (int it = 0; it < 4; it++) {
            int idx = tid + it * 256;
            int r = idx >> 3, q = idx & 7;
            int gr = row0 + r;
            la[it] = (gr < M) ? *reinterpret_cast<const float4*>(A + (size_t)gr * K + k0 + q * 4)
                              : make_float4(0.f, 0.f, 0.f, 0.f);
        }
    };
    auto sts_a = [&](const float4 la[4], int buf) {
#pragma unroll
        for (int it = 0; it < 4; it++) {
            int idx = tid + it * 256;
            int r = idx >> 3, q = idx & 7;
            As[buf][q * 4 + 0][r] = la[it].x;
            As[buf][q * 4 + 1][r] = la[it].y;
            As[buf][q * 4 + 2][r] = la[it].z;
            As[buf][q * 4 + 3][r] = la[it].w;
        }
    };

    {
        float4 la[4];
        ldg_a(0, la);
        cp_w(0, 0);
        sts_a(la, 0);
        cp_wait_all();
    }
    __syncthreads();

    for (int t = 0; t < total; t++) {
        int cur = t & 1;
        float4 la[4];
        if (t + 1 < total) { ldg_a(t + 1, la); cp_w(t + 1, cur ^ 1); }
#pragma unroll
        for (int kk = 0; kk < 32; kk++) {
            unsigned long long a2[4];
#pragma unroll
            for (int p = 0; p < 4; p++)
                a2[p] = *reinterpret_cast<const unsigned long long*>(&As[cur][kk][ty * 8 + 2 * p]);
            unsigned long long wd[8];
#pragma unroll
            for (int j = 0; j < 8; j++) wd[j] = dup_x2(Ws[cur][kk][tx + 16 * j]);
#pragma unroll
            for (int p = 0; p < 4; p++)
#pragma unroll
                for (int j = 0; j < 8; j++) fma_x2(acc[p][j], a2[p], wd[j]);
        }
        if (MEAN && t == nt1 - 1) {
#pragma unroll
            for (int p = 0; p < 4; p++) {
                int gr0 = row0 + ty * 8 + 2 * p;
                int gr1 = gr0 + 1;
                float c0 = (gr0 < M) ? cnt[gr0] : 1.f;
                float c1 = (gr1 < M) ? cnt[gr1] : 1.f;
                unsigned long long invp = pack_x2(1.f / fmaxf(c0, 1.f), 1.f / fmaxf(c1, 1.f));
#pragma unroll
                for (int j = 0; j < 8; j++) mul_x2(acc[p][j], invp);
            }
        }
        if (t + 1 < total) { sts_a(la, cur ^ 1); cp_wait_all(); }
        __syncthreads();
    }

    float bj[8];
#pragma unroll
    for (int j = 0; j < 8; j++) bj[j] = bias[tx + 16 * j];

#pragma unroll
    for (int p = 0; p < 4; p++) {
        int gr0 = row0 + ty * 8 + 2 * p;
        int gr1 = gr0 + 1;
        float r0[8], r1[8];
#pragma unroll
        for (int j = 0; j < 8; j++) {
            unpack_x2(acc[p][j], r0[j], r1[j]);
            r0[j] += bj[j]; r1[j] += bj[j];
            if (RELU) { r0[j] = fmaxf(r0[j], 0.f); r1[j] = fmaxf(r1[j], 0.f); }
        }
        if (gr0 < M) {
#pragma unroll
            for (int j = 0; j < 8; j++) out[(size_t)gr0 * 128 + tx + 16 * j] = r0[j];
        }
        if (gr1 < M) {
#pragma unroll
            for (int j = 0; j < 8; j++) out[(size_t)gr1 * 128 + tx + 16 * j] = r1[j];
        }
    }
}

// ---------------- plain gemm kernel (combine2 user, combine3 email) --------------
template<bool HAS_A2, bool RELU, bool MEAN>
__global__ void __launch_bounds__(256, 2)
gemm_combine(const float* __restrict__ A1, int K1,
             const float* __restrict__ W1T,
             const float* __restrict__ A2,
             const float* __restrict__ W2T,
             const float* __restrict__ bias,
             const float* __restrict__ cnt,
             float* __restrict__ out, int M)
{
    gemm_body<HAS_A2, RELU, MEAN>(blockIdx.x, A1, K1, W1T, A2, W2T, bias, cnt, out, M);
}

// ---------------- fused: gemm (1 of each 11 bids) + scatter (10 of 11) -----------
// Interleaved assignment keeps memory-bound scatter CTAs resident alongside
// FMA-bound gemm CTAs throughout the launch.
template<bool HAS_A2, bool RELU, bool MEAN>
__global__ void __launch_bounds__(256, 2)
fused_gemm_scatter(const float* __restrict__ A1, int K1,
                   const float* __restrict__ W1T,
                   const float* __restrict__ A2,
                   const float* __restrict__ W2T,
                   const float* __restrict__ bias,
                   const float* __restrict__ cnt,
                   float* __restrict__ out, int M,
                   const int* __restrict__ esrc, const int* __restrict__ edst,
                   const float* __restrict__ xsrc,
                   float* __restrict__ accum, float* __restrict__ scnt, int doCnt)
{
    int bid = blockIdx.x;
    int g = bid / 11;
    if (bid % 11 == 0) {
        gemm_body<HAS_A2, RELU, MEAN>(g, A1, K1, W1T, A2, W2T, bias, cnt, out, M);
    } else {
        int sbid = bid - g - 1;              // compact index over non-gemm bids
        int swarp = sbid * 8 + (threadIdx.x >> 5);
        scatter_body(swarp, threadIdx.x & 31, esrc, edst, xsrc, accum, scnt, doCnt != 0);
    }
}

// ---------------- B-spline bases (uniform grid, grid_size=5, k=3 -> 8 bases) ----
__device__ __forceinline__ void bspline8(float x, float b[8]) {
    const float hstep = 2.0f / 5.0f;
    float g[12];
#pragma unroll
    for (int t = 0; t < 12; t++) g[t] = (float)(t - 3) * hstep - 1.0f;
    float p0[11], p1[10], p2[9];
#pragma unroll
    for (int t = 0; t < 11; t++) p0[t] = (x >= g[t] && x < g[t + 1]) ? 1.0f : 0.0f;
#pragma unroll
    for (int t = 0; t < 10; t++)
        p1[t] = ((x - g[t]) * (1.0f / (g[t + 1] - g[t]))) * p0[t]
              + ((g[t + 2] - x) * (1.0f / (g[t + 2] - g[t + 1]))) * p0[t + 1];
#pragma unroll
    for (int t = 0; t < 9; t++)
        p2[t] = ((x - g[t]) * (1.0f / (g[t + 2] - g[t]))) * p1[t]
              + ((g[t + 3] - x) * (1.0f / (g[t + 3] - g[t + 1]))) * p1[t + 1];
#pragma unroll
    for (int t = 0; t < 8; t++)
        b[t] = ((x - g[t]) * (1.0f / (g[t + 3] - g[t]))) * p2[t]
             + ((g[t + 4] - x) * (1.0f / (g[t + 4] - g[t + 1]))) * p2[t + 1];
}

__device__ __forceinline__ float silu(float x) {
    return x / (1.0f + __expf(-x));
}

// ---------------- KAN layer 1 (R4-sub version, part of 2019.5us binary) ----------
__global__ void __launch_bounds__(256)
kan1_kernel(const float* __restrict__ x,
            const float* __restrict__ spline,
            const float* __restrict__ scaler,
            const float* __restrict__ basew,
            float* __restrict__ out, int M)
{
    __shared__ __align__(16) float Bs[2][32][130];
    __shared__ __align__(16) float Ws[2][32][66];
    int tid = threadIdx.x;
    int ty = tid >> 4, tx = tid & 15;
    int row0 = blockIdx.x * 128;
    unsigned long long acc[4][4];
#pragma unroll
    for (int p = 0; p < 4; p++)
#pragma unroll
        for (int j = 0; j < 4; j++) acc[p][j] = 0ULL;

    auto fill_chunk = [&](int c, float nb[2][8], float nw[8]) {
        int f0 = c * 4;
#pragma unroll
        for (int it = 0; it < 2; it++) {
            int p = tid + it * 256;
            int feat = p & 3, r = p >> 2;
            int gr = row0 + r;
            float xv = (gr < M) ? x[(size_t)gr * 128 + f0 + feat] : 0.f;
            bspline8(xv, nb[it]);
        }
#pragma unroll
        for (int it = 0; it < 8; it++) {
            int idx = tid + it * 256;
            int kk = idx & 31, col = idx >> 5;
            nw[it] = spline[(size_t)col * 1024 + f0 * 8 + kk] * scaler[col * 128 + f0 + (kk >> 3)];
        }
    };
    auto sts_chunk = [&](const float nb[2][8], const float nw[8], int buf) {
#pragma unroll
        for (int it = 0; it < 2; it++) {
            int p = tid + it * 256;
            int feat = p & 3, r = p >> 2;
#pragma unroll
            for (int t = 0; t < 8; t++) Bs[buf][feat * 8 + t][r] = nb[it][t];
        }
#pragma unroll
        for (int it = 0; it < 8; it++) {
            int idx = tid + it * 256;
            Ws[buf][idx & 31][idx >> 5] = nw[it];
        }
    };

    {
        float nb[2][8], nw[8];
        fill_chunk(0, nb, nw);
        sts_chunk(nb, nw, 0);
    }
    __syncthreads();

    for (int c = 0; c < 32; c++) {
        int cur = c & 1;
        float nb[2][8], nw[8];
        if (c + 1 < 32) fill_chunk(c + 1, nb, nw);
#pragma unroll
        for (int kk = 0; kk < 32; kk++) {
            unsigned long long a2[4];
#pragma unroll
            for (int p = 0; p < 4; p++)
                a2[p] = *reinterpret_cast<const unsigned long long*>(&Bs[cur][kk][ty * 8 + 2 * p]);
            unsigned long long wd[4];
#pragma unroll
            for (int j = 0; j < 4; j++) wd[j] = dup_x2(Ws[cur][kk][tx + 16 * j]);
#pragma unroll
            for (int p = 0; p < 4; p++)
#pragma unroll
                for (int j = 0; j < 4; j++) fma_x2(acc[p][j], a2[p], wd[j]);
        }
        if (c + 1 < 32) sts_chunk(nb, nw, cur ^ 1);
        __syncthreads();
    }

    for (int f0 = 0; f0 < 128; f0 += 32) {
#pragma unroll
        for (int it = 0; it < 16; it++) {
            int p = tid + it * 256;
            int feat = p & 31, r = p >> 5;
            int gr = row0 + r;
            float xv = (gr < M) ? x[(size_t)gr * 128 + f0 + feat] : 0.f;
            Bs[0][feat][r] = silu(xv);
        }
#pragma unroll
        for (int it = 0; it < 8; it++) {
            int idx = tid + it * 256;
            int kk = idx & 31, col = idx >> 5;
            Ws[0][kk][col] = basew[(size_t)col * 128 + f0 + kk];
        }
        __syncthreads();
#pragma unroll
        for (int kk = 0; kk < 32; kk++) {
            unsigned long long a2[4];
#pragma unroll
            for (int p = 0; p < 4; p++)
                a2[p] = *reinterpret_cast<const unsigned long long*>(&Bs[0][kk][ty * 8 + 2 * p]);
            unsigned long long wd[4];
#pragma unroll
            for (int j = 0; j < 4; j++) wd[j] = dup_x2(Ws[0][kk][tx + 16 * j]);
#pragma unroll
            for (int p = 0; p < 4; p++)
#pragma unroll
                for (int j = 0; j < 4; j++) fma_x2(acc[p][j], a2[p], wd[j]);
        }
        __syncthreads();
    }

#pragma unroll
    for (int p = 0; p < 4; p++) {
        int gr0 = row0 + ty * 8 + 2 * p;
        int gr1 = gr0 + 1;
        float r0[4], r1[4];
#pragma unroll
        for (int j = 0; j < 4; j++) unpack_x2(acc[p][j], r0[j], r1[j]);
        if (gr0 < M) {
#pragma unroll
            for (int j = 0; j < 4; j++) out[(size_t)gr0 * 64 + tx + 16 * j] = r0[j];
        }
        if (gr1 < M) {
#pragma unroll
            for (int j = 0; j < 4; j++) out[(size_t)gr1 * 64 + tx + 16 * j] = r1[j];
        }
    }
}

// ---------------- KAN layer 2: [M,64] -> [M,2], one thread per row ----------------
__global__ void kan2_kernel(const float* __restrict__ hin,
                            const float* __restrict__ spline,
                            const float* __restrict__ scaler,
                            const float* __restrict__ basew,
                            float* __restrict__ out, int M)
{
    __shared__ float sh[128][65];
    __shared__ float sw[2][64][8];
    __shared__ float sb[2][64];
    int tid = threadIdx.x;
    int row0 = blockIdx.x * 128;
    for (int idx = tid; idx < 1024; idx += 128) {
        int o = idx >> 9, rem = idx & 511, f = rem >> 3, t = rem & 7;
        sw[o][f][t] = spline[idx] * scaler[o * 64 + f];
    }
    if (tid < 128) sb[tid >> 6][tid & 63] = basew[tid];
    for (int idx = tid; idx < 128 * 64; idx += 128) {
        int r = idx >> 6, f = idx & 63;
        int gr = row0 + r;
        sh[r][f] = (gr < M) ? hin[(size_t)gr * 64 + f] : 0.f;
    }
    __syncthreads();
    int gr = row0 + tid;
    if (gr >= M) return;
    float acc0 = 0.f, acc1 = 0.f;
    for (int f = 0; f < 64; f++) {
        float xv = sh[tid][f];
        float s = silu(xv);
        acc0 += s * sb[0][f];
        acc1 += s * sb[1][f];
        float b[8];
        bspline8(xv, b);
#pragma unroll
        for (int t = 0; t < 8; t++) {
            acc0 += b[t] * sw[0][f][t];
            acc1 += b[t] * sw[1][f][t];
        }
    }
    out[(size_t)gr * 2 + 0] = acc0;
    out[(size_t)gr * 2 + 1] = acc1;
}

// ---------------- launch ----------------
extern "C" void kernel_launch(void* const* d_in, const int* in_sizes, int n_in,
                              void* d_out, int out_size)
{
    const float* x_email    = (const float*)d_in[0];
    const int*   ei_ue      = (const int*)d_in[1];
    const int*   ei_eu      = (const int*)d_in[2];
    const float* w_email    = (const float*)d_in[3];
    const float* b_email    = (const float*)d_in[4];
    const float* emb_user   = (const float*)d_in[5];
    const float* w_l1_ue_n  = (const float*)d_in[6];
    const float* b_l1_ue    = (const float*)d_in[7];
    const float* w_l1_ue_r  = (const float*)d_in[8];
    const float* w_l1_eu_n  = (const float*)d_in[9];
    const float* b_l1_eu    = (const float*)d_in[10];
    const float* w_l1_eu_r  = (const float*)d_in[11];
    const float* w_l2_ue_n  = (const float*)d_in[12];
    const float* b_l2_ue    = (const float*)d_in[13];
    const float* w_l2_ue_r  = (const float*)d_in[14];
    const float* kan1_base   = (const float*)d_in[18];
    const float* kan1_spline = (const float*)d_in[19];
    const float* kan1_scaler = (const float*)d_in[20];
    const float* kan2_base   = (const float*)d_in[22];
    const float* kan2_spline = (const float*)d_in[23];
    const float* kan2_scaler = (const float*)d_in[24];
    float* out = (float*)d_out;

    float *xe, *accE, *accE2, *e1, *accU, *u1, *hbuf, *cntE, *cntU;
    cudaGetSymbolAddress((void**)&xe,    g_xe);
    cudaGetSymbolAddress((void**)&accE,  g_accE);
    cudaGetSymbolAddress((void**)&accE2, g_accE2);
    cudaGetSymbolAddress((void**)&e1,    g_e1);
    cudaGetSymbolAddress((void**)&accU,  g_accU);
    cudaGetSymbolAddress((void**)&u1,    g_u1);
    cudaGetSymbolAddress((void**)&hbuf,  g_h);
    cudaGetSymbolAddress((void**)&cntE,  g_cntE);
    cudaGetSymbolAddress((void**)&cntU,  g_cntU);
    float *wTe, *wT1n, *wT1r, *wT2n, *wT2r, *wT3n, *wT3r;
    cudaGetSymbolAddress((void**)&wTe,  g_wTe);
    cudaGetSymbolAddress((void**)&wT1n, g_wT1n);
    cudaGetSymbolAddress((void**)&wT1r, g_wT1r);
    cudaGetSymbolAddress((void**)&wT2n, g_wT2n);
    cudaGetSymbolAddress((void**)&wT2r, g_wT2r);
    cudaGetSymbolAddress((void**)&wT3n, g_wT3n);
    cudaGetSymbolAddress((void**)&wT3r, g_wT3r);

    const int gE = (NE + 127) / 128;   // 1563
    const int gU = (NU + 127) / 128;   // 782
    const int gScat = NEDGE / 64;      // 15625 blocks (8 warps x 8 edges)
    const int gF = gE * 11;            // 17193: 1563 gemm bids + 15630 scatter bids

    // 0: init (zero + weight transpose)
    init_kernel<<<4096, 256>>>(w_email, w_l1_ue_n, w_l1_ue_r,
                               w_l1_eu_n, w_l1_eu_r, w_l2_ue_n, w_l2_ue_r);
    // 1: F1 = email_lin GEMM  ||  scatter1 (users -> accE)
    fused_gemm_scatter<false, false, false><<<gF, 256>>>(
        x_email, 64, wTe, nullptr, nullptr, b_email, nullptr, xe, NE,
        ei_ue, ei_ue + NEDGE, emb_user, accE, cntE, 1);
    // 2: F2 = combine1-email GEMM  ||  scatter2 (emails(xe) -> accU)
    fused_gemm_scatter<true, true, true><<<gF, 256>>>(
        accE, 128, wT1n, xe, wT1r, b_l1_ue, cntE, e1, NE,
        ei_eu, ei_eu + NEDGE, xe, accU, cntU, 1);
    // 3: combine1-user
    gemm_combine<true, true, true><<<gU, 256>>>(accU, 128, wT2n,
                                                emb_user, wT2r, b_l1_eu,
                                                cntU, u1, NU);
    // 4: scatter3 (u1 -> accE2)
    scatter_kernel<<<(gScat * 256 + 255) / 256, 256>>>(ei_ue, ei_ue + NEDGE, u1,
                                                       accE2, nullptr, 0);
    // 5: combine2-email
    gemm_combine<true, true, true><<<gE, 256>>>(accE2, 128, wT3n,
                                                e1, wT3r, b_l2_ue,
                                                cntE, xe /*= e2*/, NE);
    // 6-7: KAN head
    kan1_kernel<<<gE, 256>>>(xe, kan1_spline, kan1_scaler, kan1_base, hbuf, NE);
    kan2_kernel<<<gE, 128>>>(hbuf, kan2_spline, kan2_scaler, kan2_base, out, NE);
}

// round 11
// speedup vs baseline: 1.1767x; 1.0180x over previous
#include <cuda_runtime.h>
#include <cuda_bf16.h>
#include <math.h>
#include <stdint.h>

#define NE 200000
#define NU 100000
#define NEDGE 1000000
#define HDIM 128

// ---------------- scratch (static device arrays; no allocation) ----------------
__device__ float g_xe[(size_t)NE * HDIM];
__device__ float g_accE[(size_t)NE * HDIM];
__device__ float g_accE2[(size_t)NE * HDIM];
__device__ float g_e1[(size_t)NE * HDIM];
__device__ float g_accU[(size_t)NU * HDIM];
__device__ float g_u1[(size_t)NU * HDIM];
__device__ float g_h[(size_t)NE * 64];
__device__ float g_cntE[NE];
__device__ float g_cntU[NU];
// bf16 hi/lo weight tiles, padded row stride 136 (272B -> conflict-free ldmatrix)
// order: 0=l1_ue_n 1=l1_ue_r 2=l1_eu_n 3=l1_eu_r 4=l2_ue_n 5=l2_ue_r
#define WSTRIDE 136
__device__ __align__(16) __nv_bfloat16 g_weh[128 * WSTRIDE];
__device__ __align__(16) __nv_bfloat16 g_wel[128 * WSTRIDE];
__device__ __align__(16) __nv_bfloat16 g_wh[6][128 * WSTRIDE];
__device__ __align__(16) __nv_bfloat16 g_wl[6][128 * WSTRIDE];

// ---------------- helpers ----------------
__device__ __forceinline__ void fma_x2(unsigned long long& acc, unsigned long long a,
                                       unsigned long long b) {
    asm("fma.rn.f32x2 %0, %1, %2, %0;" : "+l"(acc) : "l"(a), "l"(b));
}
__device__ __forceinline__ unsigned long long dup_x2(float v) {
    unsigned long long r;
    asm("mov.b64 %0, {%1, %1};" : "=l"(r) : "f"(v));
    return r;
}
__device__ __forceinline__ void unpack_x2(unsigned long long v, float& lo, float& hi) {
    asm("mov.b64 {%0, %1}, %2;" : "=f"(lo), "=f"(hi) : "l"(v));
}
__device__ __forceinline__ uint32_t smem_u32(const void* p) {
    return (uint32_t)__cvta_generic_to_shared(p);
}
__device__ __forceinline__ void cp_async16(uint32_t dst, const void* src) {
    asm volatile("cp.async.ca.shared.global [%0], [%1], 16;" :: "r"(dst), "l"(src));
}
__device__ __forceinline__ void cp_commit() { asm volatile("cp.async.commit_group;"); }
__device__ __forceinline__ void cp_wait_all() {
    asm volatile("cp.async.wait_group 0;" ::: "memory");
}
__device__ __forceinline__ uint32_t pack_bf16(__nv_bfloat16 a, __nv_bfloat16 b) {
    uint16_t ua = *(uint16_t*)&a, ub = *(uint16_t*)&b;
    return (uint32_t)ua | ((uint32_t)ub << 16);
}
__device__ __forceinline__ void ldsm_x4(uint32_t r[4], uint32_t addr) {
    asm volatile("ldmatrix.sync.aligned.m8n8.x4.shared.b16 {%0,%1,%2,%3}, [%4];"
                 : "=r"(r[0]), "=r"(r[1]), "=r"(r[2]), "=r"(r[3]) : "r"(addr));
}
__device__ __forceinline__ void mma_bf16(float d[4], const uint32_t a[4],
                                         uint32_t b0, uint32_t b1) {
    asm volatile(
        "mma.sync.aligned.m16n8k16.row.col.f32.bf16.bf16.f32 "
        "{%0,%1,%2,%3}, {%4,%5,%6,%7}, {%8,%9}, {%0,%1,%2,%3};"
        : "+f"(d[0]), "+f"(d[1]), "+f"(d[2]), "+f"(d[3])
        : "r"(a[0]), "r"(a[1]), "r"(a[2]), "r"(a[3]), "r"(b0), "r"(b1));
}

// ---------------- init: zero accumulators + split weights to bf16 hi/lo ----------
__global__ void init_kernel(const float* we, const float* w1n, const float* w1r,
                            const float* w2n, const float* w2r,
                            const float* w3n, const float* w3r)
{
    int i = blockIdx.x * blockDim.x + threadIdx.x;
    int stride = gridDim.x * blockDim.x;
    const int nE4 = NE * HDIM / 4, nU4 = NU * HDIM / 4;
    const int cE4 = NE / 4, cU4 = NU / 4;
    float4 z = make_float4(0.f, 0.f, 0.f, 0.f);
    float4* aE  = (float4*)g_accE;
    float4* aE2 = (float4*)g_accE2;
    float4* aU  = (float4*)g_accU;
    for (int k = i; k < nE4; k += stride) { aE[k] = z; aE2[k] = z; }
    for (int k = i; k < nU4; k += stride) aU[k] = z;
    for (int k = i; k < cE4; k += stride) ((float4*)g_cntE)[k] = z;
    for (int k = i; k < cU4; k += stride) ((float4*)g_cntU)[k] = z;
    // email weight [128 out][64 in]
    for (int k = i; k < 128 * 64; k += stride) {
        int n = k >> 6, c = k & 63;
        float w = we[n * 64 + c];
        __nv_bfloat16 h = __float2bfloat16(w);
        __nv_bfloat16 l = __float2bfloat16(w - __bfloat162float(h));
        g_weh[n * WSTRIDE + c] = h;
        g_wel[n * WSTRIDE + c] = l;
    }
    // 6 weights [128 out][128 in]
    for (int k = i; k < 6 * 128 * 128; k += stride) {
        int m = k >> 14, r = k & 16383;
        int n = r >> 7, c = r & 127;
        const float* src;
        switch (m) {
            case 0: src = w1n; break;
            case 1: src = w1r; break;
            case 2: src = w2n; break;
            case 3: src = w2r; break;
            case 4: src = w3n; break;
            default: src = w3r; break;
        }
        float w = src[n * 128 + c];
        __nv_bfloat16 h = __float2bfloat16(w);
        __nv_bfloat16 l = __float2bfloat16(w - __bfloat162float(h));
        g_wh[m][n * WSTRIDE + c] = h;
        g_wl[m][n * WSTRIDE + c] = l;
    }
}

// ---------------- edge scatter: one warp per 8 edges (MLP=8), vector RED --------
__global__ void scatter_kernel(const int* __restrict__ src, const int* __restrict__ dst,
                               const float* __restrict__ xsrc,
                               float* __restrict__ accum, float* __restrict__ cnt,
                               int doCnt)
{
    int warp = (blockIdx.x * blockDim.x + threadIdx.x) >> 5;
    int lane = threadIdx.x & 31;
    int e0 = warp * 8;
    if (e0 >= NEDGE) return;
    int4 sa = *reinterpret_cast<const int4*>(src + e0);
    int4 sb = *reinterpret_cast<const int4*>(src + e0 + 4);
    int4 da = *reinterpret_cast<const int4*>(dst + e0);
    int4 db = *reinterpret_cast<const int4*>(dst + e0 + 4);
    int s[8] = {sa.x, sa.y, sa.z, sa.w, sb.x, sb.y, sb.z, sb.w};
    int d[8] = {da.x, da.y, da.z, da.w, db.x, db.y, db.z, db.w};
    float4 v[8];
#pragma unroll
    for (int i = 0; i < 8; i++)
        v[i] = *reinterpret_cast<const float4*>(xsrc + (size_t)s[i] * HDIM + lane * 4);
#pragma unroll
    for (int i = 0; i < 8; i++) {
        float* a = accum + (size_t)d[i] * HDIM + lane * 4;
        asm volatile("red.global.add.v4.f32 [%0], {%1, %2, %3, %4};"
                     :: "l"(a), "f"(v[i].x), "f"(v[i].y), "f"(v[i].z), "f"(v[i].w) : "memory");
    }
    if (doCnt && lane == 0) {
#pragma unroll
        for (int i = 0; i < 8; i++) {
            float one = 1.0f;
            asm volatile("red.global.add.f32 [%0], %1;" :: "l"(cnt + d[i]), "f"(one) : "memory");
        }
    }
}

// ---------------- tensor-core combine GEMM (mma.sync bf16-split, 3 products) -----
// out[M,128] = epi( (A1*diag(1/max(cnt,1)) if MEAN) @ W1^T
//                   + (HAS_A2 ? A2 @ W2^T : 0) + bias ),  relu if RELU
// One CTA per 128 rows; warp w owns rows 16w..16w+15 x 128 cols (16 m16n8 tiles).
// smem: [Ah 34816][Al 34816][W1h][W1l][W2h][W2l] each 34816B (rows stride 272B).
#define TILEB 34816u
template<bool HAS_A2, bool RELU, bool MEAN>
__global__ void __launch_bounds__(256)
gemm_tc(const float* __restrict__ A1, int K1,
        const __nv_bfloat16* __restrict__ W1h, const __nv_bfloat16* __restrict__ W1l,
        const float* __restrict__ A2,
        const __nv_bfloat16* __restrict__ W2h, const __nv_bfloat16* __restrict__ W2l,
        const float* __restrict__ bias, const float* __restrict__ cnt,
        float* __restrict__ out, int M)
{
    extern __shared__ char dsm[];
    uint32_t smBase = smem_u32(dsm);
    const uint32_t offAH = 0, offAL = TILEB;
    const uint32_t offW1h = 2 * TILEB, offW1l = 3 * TILEB;
    const uint32_t offW2h = 4 * TILEB, offW2l = 5 * TILEB;

    int tid = threadIdx.x;
    int widx = tid >> 5, lane = tid & 31;
    int row0 = blockIdx.x * 128;

    // async W tile copies (padded layout pre-baked in gmem)
    {
        for (uint32_t i = tid * 16; i < TILEB; i += 256 * 16) {
            cp_async16(smBase + offW1h + i, (const char*)W1h + i);
            cp_async16(smBase + offW1l + i, (const char*)W1l + i);
        }
        if (HAS_A2) {
            for (uint32_t i = tid * 16; i < TILEB; i += 256 * 16) {
                cp_async16(smBase + offW2h + i, (const char*)W2h + i);
                cp_async16(smBase + offW2l + i, (const char*)W2l + i);
            }
        }
        cp_commit();
    }

    // A fp32 -> (hi,lo) bf16 conversion into smem tiles; 1/cnt folded if mean
    auto convA = [&](const float* A, int K, bool mean) {
        int r = tid >> 1;
        int half = tid & 1;
        int cw = K >> 1;
        int c0 = half * cw;
        int gr = row0 + r;
        float inv = 1.f;
        if (mean) {
            float cv = (gr < M) ? cnt[gr] : 1.f;
            inv = 1.f / fmaxf(cv, 1.f);
        }
        const float* Arow = A + (size_t)gr * K;
        char* pH = dsm + offAH + (uint32_t)r * 272u;
        char* pL = dsm + offAL + (uint32_t)r * 272u;
        for (int c = c0; c < c0 + cw; c += 4) {
            float4 a = make_float4(0.f, 0.f, 0.f, 0.f);
            if (gr < M) a = *reinterpret_cast<const float4*>(Arow + c);
            float v0 = a.x * inv, v1 = a.y * inv, v2 = a.z * inv, v3 = a.w * inv;
            __nv_bfloat16 h0 = __float2bfloat16(v0), h1 = __float2bfloat16(v1);
            __nv_bfloat16 h2 = __float2bfloat16(v2), h3 = __float2bfloat16(v3);
            __nv_bfloat16 l0 = __float2bfloat16(v0 - __bfloat162float(h0));
            __nv_bfloat16 l1 = __float2bfloat16(v1 - __bfloat162float(h1));
            __nv_bfloat16 l2 = __float2bfloat16(v2 - __bfloat162float(h2));
            __nv_bfloat16 l3 = __float2bfloat16(v3 - __bfloat162float(h3));
            *(uint32_t*)(pH + c * 2)     = pack_bf16(h0, h1);
            *(uint32_t*)(pH + c * 2 + 4) = pack_bf16(h2, h3);
            *(uint32_t*)(pL + c * 2)     = pack_bf16(l0, l1);
            *(uint32_t*)(pL + c * 2 + 4) = pack_bf16(l2, l3);
        }
    };

    float acc[16][4];
#pragma unroll
    for (int t = 0; t < 16; t++)
#pragma unroll
        for (int q = 0; q < 4; q++) acc[t][q] = 0.f;

    // per-lane ldmatrix address components
    uint32_t aRow = (uint32_t)(widx * 16 + (lane & 15));
    uint32_t aK8  = (uint32_t)((lane >> 4) * 8);
    uint32_t wN   = (uint32_t)((lane >> 4) * 8 + (lane & 7));
    uint32_t wK8  = (uint32_t)(((lane >> 3) & 1) * 8);

    const int nph = HAS_A2 ? 2 : 1;
    for (int ph = 0; ph < nph; ph++) {
        const float* A = ph ? A2 : A1;
        int K = ph ? 128 : K1;
        uint32_t offh = ph ? offW2h : offW1h;
        uint32_t offl = ph ? offW2l : offW1l;
        if (ph) __syncthreads();             // all warps done reading A smem
        convA(A, K, MEAN && ph == 0);
        if (ph == 0) cp_wait_all();
        __syncthreads();

        int ksteps = K >> 4;
#pragma unroll 1
        for (int ks = 0; ks < ksteps; ks++) {
            uint32_t kb = (uint32_t)(ks * 16);
            uint32_t ah[4], al[4];
            uint32_t aoff = (aRow * WSTRIDE + kb + aK8) * 2;
            ldsm_x4(ah, smBase + offAH + aoff);
            ldsm_x4(al, smBase + offAL + aoff);
#pragma unroll
            for (int tp = 0; tp < 8; tp++) {
                uint32_t woff = (((uint32_t)tp * 16 + wN) * WSTRIDE + kb + wK8) * 2;
                uint32_t bh[4], bl[4];
                ldsm_x4(bh, smBase + offh + woff);
                ldsm_x4(bl, smBase + offl + woff);
                mma_bf16(acc[tp * 2],     ah, bh[0], bh[1]);
                mma_bf16(acc[tp * 2],     ah, bl[0], bl[1]);
                mma_bf16(acc[tp * 2],     al, bh[0], bh[1]);
                mma_bf16(acc[tp * 2 + 1], ah, bh[2], bh[3]);
                mma_bf16(acc[tp * 2 + 1], ah, bl[2], bl[3]);
                mma_bf16(acc[tp * 2 + 1], al, bh[2], bh[3]);
            }
        }
    }

    // epilogue: tile nt regs c0,c1 -> (row0l, col..col+1); c2,c3 -> row0l+8
    int r0l = widx * 16 + (lane >> 2);
    int gr0 = row0 + r0l, gr1 = gr0 + 8;
#pragma unroll
    for (int nt = 0; nt < 16; nt++) {
        int col = nt * 8 + (lane & 3) * 2;
        float b0 = bias[col], b1 = bias[col + 1];
        float d0 = acc[nt][0] + b0, d1 = acc[nt][1] + b1;
        float d2 = acc[nt][2] + b0, d3 = acc[nt][3] + b1;
        if (RELU) {
            d0 = fmaxf(d0, 0.f); d1 = fmaxf(d1, 0.f);
            d2 = fmaxf(d2, 0.f); d3 = fmaxf(d3, 0.f);
        }
        if (gr0 < M) *reinterpret_cast<float2*>(out + (size_t)gr0 * 128 + col) = make_float2(d0, d1);
        if (gr1 < M) *reinterpret_cast<float2*>(out + (size_t)gr1 * 128 + col) = make_float2(d2, d3);
    }
}

// ---------------- B-spline bases (uniform grid, grid_size=5, k=3 -> 8 bases) ----
__device__ __forceinline__ void bspline8(float x, float b[8]) {
    const float hstep = 2.0f / 5.0f;
    float g[12];
#pragma unroll
    for (int t = 0; t < 12; t++) g[t] = (float)(t - 3) * hstep - 1.0f;
    float p0[11], p1[10], p2[9];
#pragma unroll
    for (int t = 0; t < 11; t++) p0[t] = (x >= g[t] && x < g[t + 1]) ? 1.0f : 0.0f;
#pragma unroll
    for (int t = 0; t < 10; t++)
        p1[t] = ((x - g[t]) * (1.0f / (g[t + 1] - g[t]))) * p0[t]
              + ((g[t + 2] - x) * (1.0f / (g[t + 2] - g[t + 1]))) * p0[t + 1];
#pragma unroll
    for (int t = 0; t < 9; t++)
        p2[t] = ((x - g[t]) * (1.0f / (g[t + 2] - g[t]))) * p1[t]
              + ((g[t + 3] - x) * (1.0f / (g[t + 3] - g[t + 1]))) * p1[t + 1];
#pragma unroll
    for (int t = 0; t < 8; t++)
        b[t] = ((x - g[t]) * (1.0f / (g[t + 3] - g[t]))) * p2[t]
             + ((g[t + 4] - x) * (1.0f / (g[t + 4] - g[t + 1]))) * p2[t + 1];
}

__device__ __forceinline__ float silu(float x) {
    return x / (1.0f + __expf(-x));
}

// ---------------- KAN layer 1 (unchanged, known-good) -----------------------------
__global__ void __launch_bounds__(256)
kan1_kernel(const float* __restrict__ x,
            const float* __restrict__ spline,
            const float* __restrict__ scaler,
            const float* __restrict__ basew,
            float* __restrict__ out, int M)
{
    __shared__ __align__(16) float Bs[2][32][130];
    __shared__ __align__(16) float Ws[2][32][66];
    int tid = threadIdx.x;
    int ty = tid >> 4, tx = tid & 15;
    int row0 = blockIdx.x * 128;
    unsigned long long acc[4][4];
#pragma unroll
    for (int p = 0; p < 4; p++)
#pragma unroll
        for (int j = 0; j < 4; j++) acc[p][j] = 0ULL;

    auto fill_chunk = [&](int c, float nb[2][8], float nw[8]) {
        int f0 = c * 4;
#pragma unroll
        for (int it = 0; it < 2; it++) {
            int p = tid + it * 256;
            int feat = p & 3, r = p >> 2;
            int gr = row0 + r;
            float xv = (gr < M) ? x[(size_t)gr * 128 + f0 + feat] : 0.f;
            bspline8(xv, nb[it]);
        }
#pragma unroll
        for (int it = 0; it < 8; it++) {
            int idx = tid + it * 256;
            int kk = idx & 31, col = idx >> 5;
            nw[it] = spline[(size_t)col * 1024 + f0 * 8 + kk] * scaler[col * 128 + f0 + (kk >> 3)];
        }
    };
    auto sts_chunk = [&](const float nb[2][8], const float nw[8], int buf) {
#pragma unroll
        for (int it = 0; it < 2; it++) {
            int p = tid + it * 256;
            int feat = p & 3, r = p >> 2;
#pragma unroll
            for (int t = 0; t < 8; t++) Bs[buf][feat * 8 + t][r] = nb[it][t];
        }
#pragma unroll
        for (int it = 0; it < 8; it++) {
            int idx = tid + it * 256;
            Ws[buf][idx & 31][idx >> 5] = nw[it];
        }
    };

    {
        float nb[2][8], nw[8];
        fill_chunk(0, nb, nw);
        sts_chunk(nb, nw, 0);
    }
    __syncthreads();

    for (int c = 0; c < 32; c++) {
        int cur = c & 1;
        float nb[2][8], nw[8];
        if (c + 1 < 32) fill_chunk(c + 1, nb, nw);
#pragma unroll
        for (int kk = 0; kk < 32; kk++) {
            unsigned long long a2[4];
#pragma unroll
            for (int p = 0; p < 4; p++)
                a2[p] = *reinterpret_cast<const unsigned long long*>(&Bs[cur][kk][ty * 8 + 2 * p]);
            unsigned long long wd[4];
#pragma unroll
            for (int j = 0; j < 4; j++) wd[j] = dup_x2(Ws[cur][kk][tx + 16 * j]);
#pragma unroll
            for (int p = 0; p < 4; p++)
#pragma unroll
                for (int j = 0; j < 4; j++) fma_x2(acc[p][j], a2[p], wd[j]);
        }
        if (c + 1 < 32) sts_chunk(nb, nw, cur ^ 1);
        __syncthreads();
    }

    for (int f0 = 0; f0 < 128; f0 += 32) {
#pragma unroll
        for (int it = 0; it < 16; it++) {
            int p = tid + it * 256;
            int feat = p & 31, r = p >> 5;
            int gr = row0 + r;
            float xv = (gr < M) ? x[(size_t)gr * 128 + f0 + feat] : 0.f;
            Bs[0][feat][r] = silu(xv);
        }
#pragma unroll
        for (int it = 0; it < 8; it++) {
            int idx = tid + it * 256;
            int kk = idx & 31, col = idx >> 5;
            Ws[0][kk][col] = basew[(size_t)col * 128 + f0 + kk];
        }
        __syncthreads();
#pragma unroll
        for (int kk = 0; kk < 32; kk++) {
            unsigned long long a2[4];
#pragma unroll
            for (int p = 0; p < 4; p++)
                a2[p] = *reinterpret_cast<const unsigned long long*>(&Bs[0][kk][ty * 8 + 2 * p]);
            unsigned long long wd[4];
#pragma unroll
            for (int j = 0; j < 4; j++) wd[j] = dup_x2(Ws[0][kk][tx + 16 * j]);
#pragma unroll
            for (int p = 0; p < 4; p++)
#pragma unroll
                for (int j = 0; j < 4; j++) fma_x2(acc[p][j], a2[p], wd[j]);
        }
        __syncthreads();
    }

#pragma unroll
    for (int p = 0; p < 4; p++) {
        int gr0 = row0 + ty * 8 + 2 * p;
        int gr1 = gr0 + 1;
        float r0[4], r1[4];
#pragma unroll
        for (int j = 0; j < 4; j++) unpack_x2(acc[p][j], r0[j], r1[j]);
        if (gr0 < M) {
#pragma unroll
            for (int j = 0; j < 4; j++) out[(size_t)gr0 * 64 + tx + 16 * j] = r0[j];
        }
        if (gr1 < M) {
#pragma unroll
            for (int j = 0; j < 4; j++) out[(size_t)gr1 * 64 + tx + 16 * j] = r1[j];
        }
    }
}

// ---------------- KAN layer 2 (unchanged) ----------------------------------------
__global__ void kan2_kernel(const float* __restrict__ hin,
                            const float* __restrict__ spline,
                            const float* __restrict__ scaler,
                            const float* __restrict__ basew,
                            float* __restrict__ out, int M)
{
    __shared__ float sh[128][65];
    __shared__ float sw[2][64][8];
    __shared__ float sb[2][64];
    int tid = threadIdx.x;
    int row0 = blockIdx.x * 128;
    for (int idx = tid; idx < 1024; idx += 128) {
        int o = idx >> 9, rem = idx & 511, f = rem >> 3, t = rem & 7;
        sw[o][f][t] = spline[idx] * scaler[o * 64 + f];
    }
    if (tid < 128) sb[tid >> 6][tid & 63] = basew[tid];
    for (int idx = tid; idx < 128 * 64; idx += 128) {
        int r = idx >> 6, f = idx & 63;
        int gr = row0 + r;
        sh[r][f] = (gr < M) ? hin[(size_t)gr * 64 + f] : 0.f;
    }
    __syncthreads();
    int gr = row0 + tid;
    if (gr >= M) return;
    float acc0 = 0.f, acc1 = 0.f;
    for (int f = 0; f < 64; f++) {
        float xv = sh[tid][f];
        float s = silu(xv);
        acc0 += s * sb[0][f];
        acc1 += s * sb[1][f];
        float b[8];
        bspline8(xv, b);
#pragma unroll
        for (int t = 0; t < 8; t++) {
            acc0 += b[t] * sw[0][f][t];
            acc1 += b[t] * sw[1][f][t];
        }
    }
    out[(size_t)gr * 2 + 0] = acc0;
    out[(size_t)gr * 2 + 1] = acc1;
}

// ---------------- launch ----------------
extern "C" void kernel_launch(void* const* d_in, const int* in_sizes, int n_in,
                              void* d_out, int out_size)
{
    const float* x_email    = (const float*)d_in[0];
    const int*   ei_ue      = (const int*)d_in[1];
    const int*   ei_eu      = (const int*)d_in[2];
    const float* w_email    = (const float*)d_in[3];
    const float* b_email    = (const float*)d_in[4];
    const float* emb_user   = (const float*)d_in[5];
    const float* w_l1_ue_n  = (const float*)d_in[6];
    const float* b_l1_ue    = (const float*)d_in[7];
    const float* w_l1_ue_r  = (const float*)d_in[8];
    const float* w_l1_eu_n  = (const float*)d_in[9];
    const float* b_l1_eu    = (const float*)d_in[10];
    const float* w_l1_eu_r  = (const float*)d_in[11];
    const float* w_l2_ue_n  = (const float*)d_in[12];
    const float* b_l2_ue    = (const float*)d_in[13];
    const float* w_l2_ue_r  = (const float*)d_in[14];
    const float* kan1_base   = (const float*)d_in[18];
    const float* kan1_spline = (const float*)d_in[19];
    const float* kan1_scaler = (const float*)d_in[20];
    const float* kan2_base   = (const float*)d_in[22];
    const float* kan2_spline = (const float*)d_in[23];
    const float* kan2_scaler = (const float*)d_in[24];
    float* out = (float*)d_out;

    float *xe, *accE, *accE2, *e1, *accU, *u1, *hbuf, *cntE, *cntU;
    cudaGetSymbolAddress((void**)&xe,    g_xe);
    cudaGetSymbolAddress((void**)&accE,  g_accE);
    cudaGetSymbolAddress((void**)&accE2, g_accE2);
    cudaGetSymbolAddress((void**)&e1,    g_e1);
    cudaGetSymbolAddress((void**)&accU,  g_accU);
    cudaGetSymbolAddress((void**)&u1,    g_u1);
    cudaGetSymbolAddress((void**)&hbuf,  g_h);
    cudaGetSymbolAddress((void**)&cntE,  g_cntE);
    cudaGetSymbolAddress((void**)&cntU,  g_cntU);
    __nv_bfloat16 *weh, *wel, *wh, *wl;
    cudaGetSymbolAddress((void**)&weh, g_weh);
    cudaGetSymbolAddress((void**)&wel, g_wel);
    cudaGetSymbolAddress((void**)&wh,  g_wh);
    cudaGetSymbolAddress((void**)&wl,  g_wl);
    auto WH = [&](int m) { return wh + (size_t)m * 128 * WSTRIDE; };
    auto WL = [&](int m) { return wl + (size_t)m * 128 * WSTRIDE; };

    const int gE = (NE + 127) / 128;   // 1563
    const int gU = (NU + 127) / 128;   // 782
    const int gScat = (NEDGE / 8 * 32 + 255) / 256;  // 15625

    const int SMEM_1 = (int)(4 * TILEB);   // Ah, Al, W1h, W1l
    const int SMEM_2 = (int)(6 * TILEB);   // + W2h, W2l
    cudaFuncSetAttribute(gemm_tc<false, false, false>,
                         cudaFuncAttributeMaxDynamicSharedMemorySize, SMEM_1);
    cudaFuncSetAttribute(gemm_tc<true, true, true>,
                         cudaFuncAttributeMaxDynamicSharedMemorySize, SMEM_2);

    // 0: init (zero + bf16 weight split into padded tiles)
    init_kernel<<<4096, 256>>>(w_email, w_l1_ue_n, w_l1_ue_r,
                               w_l1_eu_n, w_l1_eu_r, w_l2_ue_n, w_l2_ue_r);
    // 1: xe = x_email @ w_email^T + b_email
    gemm_tc<false, false, false><<<gE, 256, SMEM_1>>>(
        x_email, 64, weh, wel, nullptr, nullptr, nullptr, b_email, nullptr, xe, NE);
    // 2: conv1 email aggregate
    scatter_kernel<<<gScat, 256>>>(ei_ue, ei_ue + NEDGE, emb_user, accE, cntE, 1);
    // 3: conv1 email combine
    gemm_tc<true, true, true><<<gE, 256, SMEM_2>>>(
        accE, 128, WH(0), WL(0), xe, WH(1), WL(1), b_l1_ue, cntE, e1, NE);
    // 4: conv1 user aggregate
    scatter_kernel<<<gScat, 256>>>(ei_eu, ei_eu + NEDGE, xe, accU, cntU, 1);
    // 5: conv1 user combine
    gemm_tc<true, true, true><<<gU, 256, SMEM_2>>>(
        accU, 128, WH(2), WL(2), emb_user, WH(3), WL(3), b_l1_eu, cntU, u1, NU);
    // 6: conv2 email aggregate
    scatter_kernel<<<gScat, 256>>>(ei_ue, ei_ue + NEDGE, u1, accE2, nullptr, 0);
    // 7: conv2 email combine
    gemm_tc<true, true, true><<<gE, 256, SMEM_2>>>(
        accE2, 128, WH(4), WL(4), e1, WH(5), WL(5), b_l2_ue, cntE, xe, NE);
    // 8-9: KAN head
    kan1_kernel<<<gE, 256>>>(xe, kan1_spline, kan1_scaler, kan1_base, hbuf, NE);
    kan2_kernel<<<gE, 128>>>(hbuf, kan2_spline, kan2_scaler, kan2_base, out, NE);
}

// round 12
// speedup vs baseline: 1.2265x; 1.0423x over previous
#include <cuda_runtime.h>
#include <cuda_bf16.h>
#include <math.h>
#include <stdint.h>

#define NE 200000
#define NU 100000
#define NEDGE 1000000
#define HDIM 128

// ---------------- scratch (static device arrays; no allocation) ----------------
__device__ float g_xe[(size_t)NE * HDIM];
__device__ float g_accE[(size_t)NE * HDIM];
__device__ float g_accE2[(size_t)NE * HDIM];
__device__ float g_e1[(size_t)NE * HDIM];
__device__ float g_accU[(size_t)NU * HDIM];
__device__ float g_u1[(size_t)NU * HDIM];
__device__ float g_h[(size_t)NE * 64];
__device__ float g_cntE[NE];
__device__ float g_cntU[NU];
// bf16 hi/lo weight tiles, padded row stride 136 (272B -> conflict-free ldmatrix)
#define WSTRIDE 136
__device__ __align__(16) __nv_bfloat16 g_weh[128 * WSTRIDE];
__device__ __align__(16) __nv_bfloat16 g_wel[128 * WSTRIDE];
__device__ __align__(16) __nv_bfloat16 g_wh[6][128 * WSTRIDE];
__device__ __align__(16) __nv_bfloat16 g_wl[6][128 * WSTRIDE];

// ---------------- helpers ----------------
__device__ __forceinline__ void fma_x2(unsigned long long& acc, unsigned long long a,
                                       unsigned long long b) {
    asm("fma.rn.f32x2 %0, %1, %2, %0;" : "+l"(acc) : "l"(a), "l"(b));
}
__device__ __forceinline__ unsigned long long dup_x2(float v) {
    unsigned long long r;
    asm("mov.b64 %0, {%1, %1};" : "=l"(r) : "f"(v));
    return r;
}
__device__ __forceinline__ void unpack_x2(unsigned long long v, float& lo, float& hi) {
    asm("mov.b64 {%0, %1}, %2;" : "=f"(lo), "=f"(hi) : "l"(v));
}
__device__ __forceinline__ uint32_t smem_u32(const void* p) {
    return (uint32_t)__cvta_generic_to_shared(p);
}
__device__ __forceinline__ void cp_async16(uint32_t dst, const void* src) {
    asm volatile("cp.async.ca.shared.global [%0], [%1], 16;" :: "r"(dst), "l"(src));
}
__device__ __forceinline__ void cp_commit() { asm volatile("cp.async.commit_group;"); }
__device__ __forceinline__ void cp_wait_all() {
    asm volatile("cp.async.wait_group 0;" ::: "memory");
}
__device__ __forceinline__ uint32_t pack_bf16(__nv_bfloat16 a, __nv_bfloat16 b) {
    uint16_t ua = *(uint16_t*)&a, ub = *(uint16_t*)&b;
    return (uint32_t)ua | ((uint32_t)ub << 16);
}
__device__ __forceinline__ void ldsm_x4(uint32_t r[4], uint32_t addr) {
    asm volatile("ldmatrix.sync.aligned.m8n8.x4.shared.b16 {%0,%1,%2,%3}, [%4];"
                 : "=r"(r[0]), "=r"(r[1]), "=r"(r[2]), "=r"(r[3]) : "r"(addr));
}
__device__ __forceinline__ void mma_bf16(float d[4], const uint32_t a[4],
                                         uint32_t b0, uint32_t b1) {
    asm volatile(
        "mma.sync.aligned.m16n8k16.row.col.f32.bf16.bf16.f32 "
        "{%0,%1,%2,%3}, {%4,%5,%6,%7}, {%8,%9}, {%0,%1,%2,%3};"
        : "+f"(d[0]), "+f"(d[1]), "+f"(d[2]), "+f"(d[3])
        : "r"(a[0]), "r"(a[1]), "r"(a[2]), "r"(a[3]), "r"(b0), "r"(b1));
}

// ---------------- init: zero accumulators + split weights to bf16 hi/lo ----------
__global__ void init_kernel(const float* we, const float* w1n, const float* w1r,
                            const float* w2n, const float* w2r,
                            const float* w3n, const float* w3r)
{
    int i = blockIdx.x * blockDim.x + threadIdx.x;
    int stride = gridDim.x * blockDim.x;
    const int nE4 = NE * HDIM / 4, nU4 = NU * HDIM / 4;
    const int cE4 = NE / 4, cU4 = NU / 4;
    float4 z = make_float4(0.f, 0.f, 0.f, 0.f);
    float4* aE  = (float4*)g_accE;
    float4* aE2 = (float4*)g_accE2;
    float4* aU  = (float4*)g_accU;
    for (int k = i; k < nE4; k += stride) { aE[k] = z; aE2[k] = z; }
    for (int k = i; k < nU4; k += stride) aU[k] = z;
    for (int k = i; k < cE4; k += stride) ((float4*)g_cntE)[k] = z;
    for (int k = i; k < cU4; k += stride) ((float4*)g_cntU)[k] = z;
    for (int k = i; k < 128 * 64; k += stride) {
        int n = k >> 6, c = k & 63;
        float w = we[n * 64 + c];
        __nv_bfloat16 h = __float2bfloat16(w);
        __nv_bfloat16 l = __float2bfloat16(w - __bfloat162float(h));
        g_weh[n * WSTRIDE + c] = h;
        g_wel[n * WSTRIDE + c] = l;
    }
    for (int k = i; k < 6 * 128 * 128; k += stride) {
        int m = k >> 14, r = k & 16383;
        int n = r >> 7, c = r & 127;
        const float* src;
        switch (m) {
            case 0: src = w1n; break;
            case 1: src = w1r; break;
            case 2: src = w2n; break;
            case 3: src = w2r; break;
            case 4: src = w3n; break;
            default: src = w3r; break;
        }
        float w = src[n * 128 + c];
        __nv_bfloat16 h = __float2bfloat16(w);
        __nv_bfloat16 l = __float2bfloat16(w - __bfloat162float(h));
        g_wh[m][n * WSTRIDE + c] = h;
        g_wl[m][n * WSTRIDE + c] = l;
    }
}

// ---------------- edge scatter: one warp per 8 edges (MLP=8), vector RED --------
__global__ void scatter_kernel(const int* __restrict__ src, const int* __restrict__ dst,
                               const float* __restrict__ xsrc,
                               float* __restrict__ accum, float* __restrict__ cnt,
                               int doCnt)
{
    int warp = (blockIdx.x * blockDim.x + threadIdx.x) >> 5;
    int lane = threadIdx.x & 31;
    int e0 = warp * 8;
    if (e0 >= NEDGE) return;
    int4 sa = *reinterpret_cast<const int4*>(src + e0);
    int4 sb = *reinterpret_cast<const int4*>(src + e0 + 4);
    int4 da = *reinterpret_cast<const int4*>(dst + e0);
    int4 db = *reinterpret_cast<const int4*>(dst + e0 + 4);
    int s[8] = {sa.x, sa.y, sa.z, sa.w, sb.x, sb.y, sb.z, sb.w};
    int d[8] = {da.x, da.y, da.z, da.w, db.x, db.y, db.z, db.w};
    float4 v[8];
#pragma unroll
    for (int i = 0; i < 8; i++)
        v[i] = *reinterpret_cast<const float4*>(xsrc + (size_t)s[i] * HDIM + lane * 4);
#pragma unroll
    for (int i = 0; i < 8; i++) {
        float* a = accum + (size_t)d[i] * HDIM + lane * 4;
        asm volatile("red.global.add.v4.f32 [%0], {%1, %2, %3, %4};"
                     :: "l"(a), "f"(v[i].x), "f"(v[i].y), "f"(v[i].z), "f"(v[i].w) : "memory");
    }
    if (doCnt && lane == 0) {
#pragma unroll
        for (int i = 0; i < 8; i++) {
            float one = 1.0f;
            asm volatile("red.global.add.f32 [%0], %1;" :: "l"(cnt + d[i]), "f"(one) : "memory");
        }
    }
}

// ---------------- tensor-core combine GEMM (mma.sync bf16-split, 3 products) -----
// out[M,128] = epi( (A1*diag(1/max(cnt,1)) if MEAN) @ W1^T
//                   + (HAS_A2 ? A2 @ W2^T : 0) + bias ),  relu if RELU
// 8 warps: warp w owns rows (w>>1)*32..+31 x cols (w&1)*64..+63 (2x8 m16n8 tiles).
// Fragment batching: 12 LDSM then 48 MMA per k-step.
#define TILEB 34816u
template<bool HAS_A2, bool RELU, bool MEAN>
__global__ void __launch_bounds__(256)
gemm_tc(const float* __restrict__ A1, int K1,
        const __nv_bfloat16* __restrict__ W1h, const __nv_bfloat16* __restrict__ W1l,
        const float* __restrict__ A2,
        const __nv_bfloat16* __restrict__ W2h, const __nv_bfloat16* __restrict__ W2l,
        const float* __restrict__ bias, const float* __restrict__ cnt,
        float* __restrict__ out, int M)
{
    extern __shared__ char dsm[];
    uint32_t smBase = smem_u32(dsm);
    const uint32_t offAH = 0, offAL = TILEB;
    const uint32_t offW1h = 2 * TILEB, offW1l = 3 * TILEB;
    const uint32_t offW2h = 4 * TILEB, offW2l = 5 * TILEB;

    int tid = threadIdx.x;
    int widx = tid >> 5, lane = tid & 31;
    int rb = widx >> 1;          // row block 0..3 (32 rows each)
    int cb = widx & 1;           // col block 0..1 (64 cols each)
    int row0 = blockIdx.x * 128;

    // async W tile copies (padded layout pre-baked in gmem)
    {
        for (uint32_t i = tid * 16; i < TILEB; i += 256 * 16) {
            cp_async16(smBase + offW1h + i, (const char*)W1h + i);
            cp_async16(smBase + offW1l + i, (const char*)W1l + i);
        }
        if (HAS_A2) {
            for (uint32_t i = tid * 16; i < TILEB; i += 256 * 16) {
                cp_async16(smBase + offW2h + i, (const char*)W2h + i);
                cp_async16(smBase + offW2l + i, (const char*)W2l + i);
            }
        }
        cp_commit();
    }

    // A fp32 -> (hi,lo) bf16 conversion into smem tiles; 1/cnt folded if mean
    auto convA = [&](const float* A, int K, bool mean) {
        int r = tid >> 1;
        int half = tid & 1;
        int cw = K >> 1;
        int c0 = half * cw;
        int gr = row0 + r;
        float inv = 1.f;
        if (mean) {
            float cv = (gr < M) ? cnt[gr] : 1.f;
            inv = 1.f / fmaxf(cv, 1.f);
        }
        const float* Arow = A + (size_t)gr * K;
        char* pH = dsm + offAH + (uint32_t)r * 272u;
        char* pL = dsm + offAL + (uint32_t)r * 272u;
        for (int c = c0; c < c0 + cw; c += 4) {
            float4 a = make_float4(0.f, 0.f, 0.f, 0.f);
            if (gr < M) a = *reinterpret_cast<const float4*>(Arow + c);
            float v0 = a.x * inv, v1 = a.y * inv, v2 = a.z * inv, v3 = a.w * inv;
            __nv_bfloat16 h0 = __float2bfloat16(v0), h1 = __float2bfloat16(v1);
            __nv_bfloat16 h2 = __float2bfloat16(v2), h3 = __float2bfloat16(v3);
            __nv_bfloat16 l0 = __float2bfloat16(v0 - __bfloat162float(h0));
            __nv_bfloat16 l1 = __float2bfloat16(v1 - __bfloat162float(h1));
            __nv_bfloat16 l2 = __float2bfloat16(v2 - __bfloat162float(h2));
            __nv_bfloat16 l3 = __float2bfloat16(v3 - __bfloat162float(h3));
            *(uint32_t*)(pH + c * 2)     = pack_bf16(h0, h1);
            *(uint32_t*)(pH + c * 2 + 4) = pack_bf16(h2, h3);
            *(uint32_t*)(pL + c * 2)     = pack_bf16(l0, l1);
            *(uint32_t*)(pL + c * 2 + 4) = pack_bf16(l2, l3);
        }
    };

    // acc tile index: rt*8 + j (rt=row 16-tile 0..1, j=n8 tile 0..7 within 64 cols)
    float acc[16][4];
#pragma unroll
    for (int t = 0; t < 16; t++)
#pragma unroll
        for (int q = 0; q < 4; q++) acc[t][q] = 0.f;

    // per-lane ldmatrix address components
    uint32_t aRowL = (uint32_t)(lane & 15);
    uint32_t aK8   = (uint32_t)((lane >> 4) * 8);
    uint32_t wN    = (uint32_t)((lane >> 4) * 8 + (lane & 7));
    uint32_t wK8   = (uint32_t)(((lane >> 3) & 1) * 8);

    const int nph = HAS_A2 ? 2 : 1;
    for (int ph = 0; ph < nph; ph++) {
        const float* A = ph ? A2 : A1;
        int K = ph ? 128 : K1;
        uint32_t offh = ph ? offW2h : offW1h;
        uint32_t offl = ph ? offW2l : offW1l;
        if (ph) __syncthreads();             // all warps done reading A smem
        convA(A, K, MEAN && ph == 0);
        if (ph == 0) cp_wait_all();
        __syncthreads();

        int ksteps = K >> 4;
#pragma unroll 1
        for (int ks = 0; ks < ksteps; ks++) {
            uint32_t kb = (uint32_t)(ks * 16);
            // batch all fragments: 4 A + 8 W ldsm (high MLP), then 48 MMAs
            uint32_t ah[2][4], al[2][4];
#pragma unroll
            for (int rt = 0; rt < 2; rt++) {
                uint32_t aoff = (((uint32_t)(rb * 32 + rt * 16) + aRowL) * WSTRIDE + kb + aK8) * 2;
                ldsm_x4(ah[rt], smBase + offAH + aoff);
                ldsm_x4(al[rt], smBase + offAL + aoff);
            }
            uint32_t bh[4][4], bl[4][4];
#pragma unroll
            for (int tp = 0; tp < 4; tp++) {
                uint32_t woff = (((uint32_t)(cb * 64 + tp * 16) + wN) * WSTRIDE + kb + wK8) * 2;
                ldsm_x4(bh[tp], smBase + offh + woff);
                ldsm_x4(bl[tp], smBase + offl + woff);
            }
#pragma unroll
            for (int rt = 0; rt < 2; rt++) {
#pragma unroll
                for (int tp = 0; tp < 4; tp++) {
                    int t0 = rt * 8 + tp * 2;
                    mma_bf16(acc[t0],     ah[rt], bh[tp][0], bh[tp][1]);
                    mma_bf16(acc[t0],     ah[rt], bl[tp][0], bl[tp][1]);
                    mma_bf16(acc[t0],     al[rt], bh[tp][0], bh[tp][1]);
                    mma_bf16(acc[t0 + 1], ah[rt], bh[tp][2], bh[tp][3]);
                    mma_bf16(acc[t0 + 1], ah[rt], bl[tp][2], bl[tp][3]);
                    mma_bf16(acc[t0 + 1], al[rt], bh[tp][2], bh[tp][3]);
                }
            }
        }
    }

    // epilogue: tile (rt, j): rows rb*32+rt*16+(lane>>2) (+8), col cb*64+j*8+(lane&3)*2
#pragma unroll
    for (int rt = 0; rt < 2; rt++) {
        int gr0 = row0 + rb * 32 + rt * 16 + (lane >> 2);
        int gr1 = gr0 + 8;
#pragma unroll
        for (int j = 0; j < 8; j++) {
            int col = cb * 64 + j * 8 + (lane & 3) * 2;
            float b0 = bias[col], b1 = bias[col + 1];
            float* a = acc[rt * 8 + j];
            float d0 = a[0] + b0, d1 = a[1] + b1;
            float d2 = a[2] + b0, d3 = a[3] + b1;
            if (RELU) {
                d0 = fmaxf(d0, 0.f); d1 = fmaxf(d1, 0.f);
                d2 = fmaxf(d2, 0.f); d3 = fmaxf(d3, 0.f);
            }
            if (gr0 < M) *reinterpret_cast<float2*>(out + (size_t)gr0 * 128 + col) = make_float2(d0, d1);
            if (gr1 < M) *reinterpret_cast<float2*>(out + (size_t)gr1 * 128 + col) = make_float2(d2, d3);
        }
    }
}

// ---------------- B-spline bases (uniform grid, grid_size=5, k=3 -> 8 bases) ----
__device__ __forceinline__ void bspline8(float x, float b[8]) {
    const float hstep = 2.0f / 5.0f;
    float g[12];
#pragma unroll
    for (int t = 0; t < 12; t++) g[t] = (float)(t - 3) * hstep - 1.0f;
    float p0[11], p1[10], p2[9];
#pragma unroll
    for (int t = 0; t < 11; t++) p0[t] = (x >= g[t] && x < g[t + 1]) ? 1.0f : 0.0f;
#pragma unroll
    for (int t = 0; t < 10; t++)
        p1[t] = ((x - g[t]) * (1.0f / (g[t + 1] - g[t]))) * p0[t]
              + ((g[t + 2] - x) * (1.0f / (g[t + 2] - g[t + 1]))) * p0[t + 1];
#pragma unroll
    for (int t = 0; t < 9; t++)
        p2[t] = ((x - g[t]) * (1.0f / (g[t + 2] - g[t]))) * p1[t]
              + ((g[t + 3] - x) * (1.0f / (g[t + 3] - g[t + 1]))) * p1[t + 1];
#pragma unroll
    for (int t = 0; t < 8; t++)
        b[t] = ((x - g[t]) * (1.0f / (g[t + 3] - g[t]))) * p2[t]
             + ((g[t + 4] - x) * (1.0f / (g[t + 4] - g[t + 1]))) * p2[t + 1];
}

__device__ __forceinline__ float silu(float x) {
    return x / (1.0f + __expf(-x));
}

// ---------------- KAN layer 1 (unchanged, known-good) -----------------------------
__global__ void __launch_bounds__(256)
kan1_kernel(const float* __restrict__ x,
            const float* __restrict__ spline,
            const float* __restrict__ scaler,
            const float* __restrict__ basew,
            float* __restrict__ out, int M)
{
    __shared__ __align__(16) float Bs[2][32][130];
    __shared__ __align__(16) float Ws[2][32][66];
    int tid = threadIdx.x;
    int ty = tid >> 4, tx = tid & 15;
    int row0 = blockIdx.x * 128;
    unsigned long long acc[4][4];
#pragma unroll
    for (int p = 0; p < 4; p++)
#pragma unroll
        for (int j = 0; j < 4; j++) acc[p][j] = 0ULL;

    auto fill_chunk = [&](int c, float nb[2][8], float nw[8]) {
        int f0 = c * 4;
#pragma unroll
        for (int it = 0; it < 2; it++) {
            int p = tid + it * 256;
            int feat = p & 3, r = p >> 2;
            int gr = row0 + r;
            float xv = (gr < M) ? x[(size_t)gr * 128 + f0 + feat] : 0.f;
            bspline8(xv, nb[it]);
        }
#pragma unroll
        for (int it = 0; it < 8; it++) {
            int idx = tid + it * 256;
            int kk = idx & 31, col = idx >> 5;
            nw[it] = spline[(size_t)col * 1024 + f0 * 8 + kk] * scaler[col * 128 + f0 + (kk >> 3)];
        }
    };
    auto sts_chunk = [&](const float nb[2][8], const float nw[8], int buf) {
#pragma unroll
        for (int it = 0; it < 2; it++) {
            int p = tid + it * 256;
            int feat = p & 3, r = p >> 2;
#pragma unroll
            for (int t = 0; t < 8; t++) Bs[buf][feat * 8 + t][r] = nb[it][t];
        }
#pragma unroll
        for (int it = 0; it < 8; it++) {
            int idx = tid + it * 256;
            Ws[buf][idx & 31][idx >> 5] = nw[it];
        }
    };

    {
        float nb[2][8], nw[8];
        fill_chunk(0, nb, nw);
        sts_chunk(nb, nw, 0);
    }
    __syncthreads();

    for (int c = 0; c < 32; c++) {
        int cur = c & 1;
        float nb[2][8], nw[8];
        if (c + 1 < 32) fill_chunk(c + 1, nb, nw);
#pragma unroll
        for (int kk = 0; kk < 32; kk++) {
            unsigned long long a2[4];
#pragma unroll
            for (int p = 0; p < 4; p++)
                a2[p] = *reinterpret_cast<const unsigned long long*>(&Bs[cur][kk][ty * 8 + 2 * p]);
            unsigned long long wd[4];
#pragma unroll
            for (int j = 0; j < 4; j++) wd[j] = dup_x2(Ws[cur][kk][tx + 16 * j]);
#pragma unroll
            for (int p = 0; p < 4; p++)
#pragma unroll
                for (int j = 0; j < 4; j++) fma_x2(acc[p][j], a2[p], wd[j]);
        }
        if (c + 1 < 32) sts_chunk(nb, nw, cur ^ 1);
        __syncthreads();
    }

    for (int f0 = 0; f0 < 128; f0 += 32) {
#pragma unroll
        for (int it = 0; it < 16; it++) {
            int p = tid + it * 256;
            int feat = p & 31, r = p >> 5;
            int gr = row0 + r;
            float xv = (gr < M) ? x[(size_t)gr * 128 + f0 + feat] : 0.f;
            Bs[0][feat][r] = silu(xv);
        }
#pragma unroll
        for (int it = 0; it < 8; it++) {
            int idx = tid + it * 256;
            int kk = idx & 31, col = idx >> 5;
            Ws[0][kk][col] = basew[(size_t)col * 128 + f0 + kk];
        }
        __syncthreads();
#pragma unroll
        for (int kk = 0; kk < 32; kk++) {
            unsigned long long a2[4];
#pragma unroll
            for (int p = 0; p < 4; p++)
                a2[p] = *reinterpret_cast<const unsigned long long*>(&Bs[0][kk][ty * 8 + 2 * p]);
            unsigned long long wd[4];
#pragma unroll
            for (int j = 0; j < 4; j++) wd[j] = dup_x2(Ws[0][kk][tx + 16 * j]);
#pragma unroll
            for (int p = 0; p < 4; p++)
#pragma unroll
                for (int j = 0; j < 4; j++) fma_x2(acc[p][j], a2[p], wd[j]);
        }
        __syncthreads();
    }

#pragma unroll
    for (int p = 0; p < 4; p++) {
        int gr0 = row0 + ty * 8 + 2 * p;
        int gr1 = gr0 + 1;
        float r0[4], r1[4];
#pragma unroll
        for (int j = 0; j < 4; j++) unpack_x2(acc[p][j], r0[j], r1[j]);
        if (gr0 < M) {
#pragma unroll
            for (int j = 0; j < 4; j++) out[(size_t)gr0 * 64 + tx + 16 * j] = r0[j];
        }
        if (gr1 < M) {
#pragma unroll
            for (int j = 0; j < 4; j++) out[(size_t)gr1 * 64 + tx + 16 * j] = r1[j];
        }
    }
}

// ---------------- KAN layer 2 (unchanged) ----------------------------------------
__global__ void kan2_kernel(const float* __restrict__ hin,
                            const float* __restrict__ spline,
                            const float* __restrict__ scaler,
                            const float* __restrict__ basew,
                            float* __restrict__ out, int M)
{
    __shared__ float sh[128][65];
    __shared__ float sw[2][64][8];
    __shared__ float sb[2][64];
    int tid = threadIdx.x;
    int row0 = blockIdx.x * 128;
    for (int idx = tid; idx < 1024; idx += 128) {
        int o = idx >> 9, rem = idx & 511, f = rem >> 3, t = rem & 7;
        sw[o][f][t] = spline[idx] * scaler[o * 64 + f];
    }
    if (tid < 128) sb[tid >> 6][tid & 63] = basew[tid];
    for (int idx = tid; idx < 128 * 64; idx += 128) {
        int r = idx >> 6, f = idx & 63;
        int gr = row0 + r;
        sh[r][f] = (gr < M) ? hin[(size_t)gr * 64 + f] : 0.f;
    }
    __syncthreads();
    int gr = row0 + tid;
    if (gr >= M) return;
    float acc0 = 0.f, acc1 = 0.f;
    for (int f = 0; f < 64; f++) {
        float xv = sh[tid][f];
        float s = silu(xv);
        acc0 += s * sb[0][f];
        acc1 += s * sb[1][f];
        float b[8];
        bspline8(xv, b);
#pragma unroll
        for (int t = 0; t < 8; t++) {
            acc0 += b[t] * sw[0][f][t];
            acc1 += b[t] * sw[1][f][t];
        }
    }
    out[(size_t)gr * 2 + 0] = acc0;
    out[(size_t)gr * 2 + 1] = acc1;
}

// ---------------- launch ----------------
extern "C" void kernel_launch(void* const* d_in, const int* in_sizes, int n_in,
                              void* d_out, int out_size)
{
    const float* x_email    = (const float*)d_in[0];
    const int*   ei_ue      = (const int*)d_in[1];
    const int*   ei_eu      = (const int*)d_in[2];
    const float* w_email    = (const float*)d_in[3];
    const float* b_email    = (const float*)d_in[4];
    const float* emb_user   = (const float*)d_in[5];
    const float* w_l1_ue_n  = (const float*)d_in[6];
    const float* b_l1_ue    = (const float*)d_in[7];
    const float* w_l1_ue_r  = (const float*)d_in[8];
    const float* w_l1_eu_n  = (const float*)d_in[9];
    const float* b_l1_eu    = (const float*)d_in[10];
    const float* w_l1_eu_r  = (const float*)d_in[11];
    const float* w_l2_ue_n  = (const float*)d_in[12];
    const float* b_l2_ue    = (const float*)d_in[13];
    const float* w_l2_ue_r  = (const float*)d_in[14];
    const float* kan1_base   = (const float*)d_in[18];
    const float* kan1_spline = (const float*)d_in[19];
    const float* kan1_scaler = (const float*)d_in[20];
    const float* kan2_base   = (const float*)d_in[22];
    const float* kan2_spline = (const float*)d_in[23];
    const float* kan2_scaler = (const float*)d_in[24];
    float* out = (float*)d_out;

    float *xe, *accE, *accE2, *e1, *accU, *u1, *hbuf, *cntE, *cntU;
    cudaGetSymbolAddress((void**)&xe,    g_xe);
    cudaGetSymbolAddress((void**)&accE,  g_accE);
    cudaGetSymbolAddress((void**)&accE2, g_accE2);
    cudaGetSymbolAddress((void**)&e1,    g_e1);
    cudaGetSymbolAddress((void**)&accU,  g_accU);
    cudaGetSymbolAddress((void**)&u1,    g_u1);
    cudaGetSymbolAddress((void**)&hbuf,  g_h);
    cudaGetSymbolAddress((void**)&cntE,  g_cntE);
    cudaGetSymbolAddress((void**)&cntU,  g_cntU);
    __nv_bfloat16 *weh, *wel, *wh, *wl;
    cudaGetSymbolAddress((void**)&weh, g_weh);
    cudaGetSymbolAddress((void**)&wel, g_wel);
    cudaGetSymbolAddress((void**)&wh,  g_wh);
    cudaGetSymbolAddress((void**)&wl,  g_wl);
    auto WH = [&](int m) { return wh + (size_t)m * 128 * WSTRIDE; };
    auto WL = [&](int m) { return wl + (size_t)m * 128 * WSTRIDE; };

    const int gE = (NE + 127) / 128;   // 1563
    const int gU = (NU + 127) / 128;   // 782
    const int gScat = (NEDGE / 8 * 32 + 255) / 256;  // 15625

    const int SMEM_1 = (int)(4 * TILEB);
    const int SMEM_2 = (int)(6 * TILEB);
    cudaFuncSetAttribute(gemm_tc<false, false, false>,
                         cudaFuncAttributeMaxDynamicSharedMemorySize, SMEM_1);
    cudaFuncSetAttribute(gemm_tc<true, true, true>,
                         cudaFuncAttributeMaxDynamicSharedMemorySize, SMEM_2);

    init_kernel<<<4096, 256>>>(w_email, w_l1_ue_n, w_l1_ue_r,
                               w_l1_eu_n, w_l1_eu_r, w_l2_ue_n, w_l2_ue_r);
    gemm_tc<false, false, false><<<gE, 256, SMEM_1>>>(
        x_email, 64, weh, wel, nullptr, nullptr, nullptr, b_email, nullptr, xe, NE);
    scatter_kernel<<<gScat, 256>>>(ei_ue, ei_ue + NEDGE, emb_user, accE, cntE, 1);
    gemm_tc<true, true, true><<<gE, 256, SMEM_2>>>(
        accE, 128, WH(0), WL(0), xe, WH(1), WL(1), b_l1_ue, cntE, e1, NE);
    scatter_kernel<<<gScat, 256>>>(ei_eu, ei_eu + NEDGE, xe, accU, cntU, 1);
    gemm_tc<true, true, true><<<gU, 256, SMEM_2>>>(
        accU, 128, WH(2), WL(2), emb_user, WH(3), WL(3), b_l1_eu, cntU, u1, NU);
    scatter_kernel<<<gScat, 256>>>(ei_ue, ei_ue + NEDGE, u1, accE2, nullptr, 0);
    gemm_tc<true, true, true><<<gE, 256, SMEM_2>>>(
        accE2, 128, WH(4), WL(4), e1, WH(5), WL(5), b_l2_ue, cntE, xe, NE);
    kan1_kernel<<<gE, 256>>>(xe, kan1_spline, kan1_scaler, kan1_base, hbuf, NE);
    kan2_kernel<<<gE, 128>>>(hbuf, kan2_spline, kan2_scaler, kan2_base, out, NE);
}